// round 9
// baseline (speedup 1.0000x reference)
#include <cuda_runtime.h>
#include <cuda_bf16.h>
#include <math.h>
#include <stdint.h>

// Problem dims
#define BB 2
#define HH 32
#define SS 2048
#define DD 128
#define BHN (BB*HH)

// Output layout (floats), concatenated in reference return order
#define OFF_ATTN   ((size_t)0)
#define OFF_KQ     ((size_t)16777216)
#define OFF_KSCALE ((size_t)33554432)
#define OFF_VQ     ((size_t)33562624)
#define OFF_VSCALE ((size_t)50339840)
#define OFF_KSPV   ((size_t)50470912)
#define OFF_KSPI   ((size_t)50601984)
#define OFF_VSPV   ((size_t)50733056)
#define OFF_VSPI   ((size_t)51257344)

// Scratch (device globals: no allocation allowed)
__device__ float g_krot[BB*HH*SS*DD];
__device__ float g_invf[64];
__device__ float g_cos[SS*64];
__device__ float g_sin[SS*64];
// Split-bf16 planes, pre-swizzled rows of 256B (16 x 16B chunks, chunk ^= row&7)
__device__ uint4 g_qh[BHN*SS*16];
__device__ uint4 g_ql[BHN*SS*16];
__device__ uint4 g_kh[BHN*SS*16];
__device__ uint4 g_kl[BHN*SS*16];
__device__ uint4 g_vh[BHN*SS*16];
__device__ uint4 g_vl[BHN*SS*16];

// ===========================================================================
// helpers
// ===========================================================================
__device__ __forceinline__ uint32_t smem_u32(const void* p) {
    uint32_t a;
    asm("{ .reg .u64 t; cvta.to.shared.u64 t, %1; cvt.u32.u64 %0, t; }"
        : "=r"(a) : "l"(p));
    return a;
}

// swizzled byte offset within a [rows][128 bf16] tile, 256B row pitch
__device__ __forceinline__ int soff(int r, int d) {
    return r * 256 + ((((d >> 3) ^ (r & 7)) & 15) << 4) + ((d & 7) << 1);
}

#define LDSM4(r, a) \
    asm volatile("ldmatrix.sync.aligned.m8n8.x4.shared.b16 {%0,%1,%2,%3}, [%4];" \
        : "=r"((r)[0]), "=r"((r)[1]), "=r"((r)[2]), "=r"((r)[3]) : "r"(a))
#define LDSM4T(r, a) \
    asm volatile("ldmatrix.sync.aligned.m8n8.x4.trans.shared.b16 {%0,%1,%2,%3}, [%4];" \
        : "=r"((r)[0]), "=r"((r)[1]), "=r"((r)[2]), "=r"((r)[3]) : "r"(a))

#define MMA16816(c, a0,a1,a2,a3, b0,b1) \
    asm volatile("mma.sync.aligned.m16n8k16.row.col.f32.bf16.bf16.f32 " \
        "{%0,%1,%2,%3}, {%4,%5,%6,%7}, {%8,%9}, {%0,%1,%2,%3};" \
        : "+f"((c)[0]), "+f"((c)[1]), "+f"((c)[2]), "+f"((c)[3]) \
        : "r"(a0), "r"(a1), "r"(a2), "r"(a3), "r"(b0), "r"(b1))

__device__ __forceinline__ float ex2f(float x) {
    float y;
    asm("ex2.approx.f32 %0, %1;" : "=f"(y) : "f"(x));
    return y;
}

// bf16 split: hi = bf16(a,b), lo = bf16(residuals). hi low half = a.
__device__ __forceinline__ uint32_t bsplit2(float a, float b, uint32_t& lo) {
    __nv_bfloat16 ha = __float2bfloat16_rn(a);
    __nv_bfloat16 hb = __float2bfloat16_rn(b);
    float ra = a - __bfloat162float(ha);
    float rb = b - __bfloat162float(hb);
    __nv_bfloat16 la = __float2bfloat16_rn(ra);
    __nv_bfloat16 lb = __float2bfloat16_rn(rb);
    lo = ((uint32_t)__bfloat16_as_ushort(lb) << 16) | (uint32_t)__bfloat16_as_ushort(la);
    return ((uint32_t)__bfloat16_as_ushort(hb) << 16) | (uint32_t)__bfloat16_as_ushort(ha);
}

__device__ __forceinline__ void split8(const float* v, uint4& hi, uint4& lo) {
    uint32_t l0, l1, l2, l3;
    hi.x = bsplit2(v[0], v[1], l0);
    hi.y = bsplit2(v[2], v[3], l1);
    hi.z = bsplit2(v[4], v[5], l2);
    hi.w = bsplit2(v[6], v[7], l3);
    lo.x = l0; lo.y = l1; lo.z = l2; lo.w = l3;
}

// ---------------------------------------------------------------------------
// inv_freq: 64 double pow calls only (bit-identical to before).
// ---------------------------------------------------------------------------
__global__ void invf_kernel() {
    int j = threadIdx.x;
    double e = (double)(2 * j) / 128.0;
    double p = pow(10000.0, e);
    float pf = (float)p;
    g_invf[j] = 1.0f / pf;
}

// ---------------------------------------------------------------------------
// Custom double sincos: Cody-Waite 2-term pi/2 reduction + fdlibm minimax
// polys. Input is an f32 angle in [0, 2048): k = rint(x*2/pi) <= 1304, and
// pio2_1 has 33 mantissa bits so k*pio2_1 is exact. Abs accuracy ~1e-16,
// orders below f32 ulp => rounds to the same f32 as libm double sin/cos.
// ---------------------------------------------------------------------------
__device__ __forceinline__ void dsincos_f(float angf, float* cs, float* sn) {
    const double pio2_1  = 1.57079632673412561417e+00;  // 33 bits of pi/2
    const double pio2_1t = 6.07710050650619224932e-11;  // pi/2 - pio2_1
    double x = (double)angf;
    double kd = rint(x * 6.36619772367581382433e-01);   // 2/pi
    double r = x - kd * pio2_1;
    r = r - kd * pio2_1t;
    double z = r * r;
    // sin(r), fdlibm __kernel_sin coefficients
    double ps = 1.58969099521155010221e-10;
    ps = ps * z + -2.50507602534068634195e-08;
    ps = ps * z +  2.75573137070700676789e-06;
    ps = ps * z + -1.98412698298579493134e-04;
    ps = ps * z +  8.33333333332248946124e-03;
    ps = ps * z + -1.66666666666666324348e-01;
    double s = r + r * z * ps;
    // cos(r), fdlibm __kernel_cos coefficients (plain Horner; f32 target)
    double pc = -1.13596475577881948265e-11;
    pc = pc * z +  2.08757232129817482790e-09;
    pc = pc * z + -2.75573143513906633035e-07;
    pc = pc * z +  2.48015872894767294178e-05;
    pc = pc * z + -1.38888888888741095749e-03;
    pc = pc * z +  4.16666666666666019037e-02;
    double c = 1.0 + z * (-0.5 + z * pc);
    int q = ((int)kd) & 3;
    double sv, cv;
    if (q == 0)      { sv = s;  cv = c;  }
    else if (q == 1) { sv = c;  cv = -s; }
    else if (q == 2) { sv = -s; cv = -c; }
    else             { sv = -c; cv = s;  }
    *sn = (float)sv;
    *cs = (float)cv;
}

// ---------------------------------------------------------------------------
// RoPE cos/sin table: f32 angle = f32(s) * invf (same rounding as reference),
// then custom double sincos (was: libm double sin/cos, ~5ms of FP64).
// ---------------------------------------------------------------------------
__global__ void table_kernel() {
    int s = blockIdx.x;
    int j = threadIdx.x;
    float ang = __fmul_rn((float)s, g_invf[j]);
    float c, sn;
    dsincos_f(ang, &c, &sn);
    g_cos[s * 64 + j] = c;
    g_sin[s * 64 + j] = sn;
}

// ---------------------------------------------------------------------------
// Fused RoPE + split-bf16 planes. One thread = one 8-elem lower chunk + its
// upper partner (d0 and d0+64). Writes krot f32 (for kquant) + qh/ql/kh/kl.
// ---------------------------------------------------------------------------
__global__ void rope_split_kernel(const float* __restrict__ q, const float* __restrict__ k,
                                  const int* __restrict__ pos_ids) {
    int idx = blockIdx.x * 256 + threadIdx.x;
    if (idx >= BHN * SS * 8) return;
    int c = idx & 7;
    int s = (idx >> 3) & 2047;
    int bh = idx >> 14;
    int b = bh >> 5;
    int pos = pos_ids[b * SS + s];
    int d0 = c * 8;
    size_t rb = ((size_t)bh * SS + s) * DD;

    float xq[8], yq[8], xk[8], yk[8], cs[8], sn[8];
    *(float4*)&xq[0] = *(const float4*)&q[rb + d0];
    *(float4*)&xq[4] = *(const float4*)&q[rb + d0 + 4];
    *(float4*)&yq[0] = *(const float4*)&q[rb + d0 + 64];
    *(float4*)&yq[4] = *(const float4*)&q[rb + d0 + 68];
    *(float4*)&xk[0] = *(const float4*)&k[rb + d0];
    *(float4*)&xk[4] = *(const float4*)&k[rb + d0 + 4];
    *(float4*)&yk[0] = *(const float4*)&k[rb + d0 + 64];
    *(float4*)&yk[4] = *(const float4*)&k[rb + d0 + 68];
    #pragma unroll
    for (int i = 0; i < 8; i++) {
        cs[i] = g_cos[pos * 64 + d0 + i];
        sn[i] = g_sin[pos * 64 + d0 + i];
    }

    float loq[8], upq[8], lok[8], upk[8];
    #pragma unroll
    for (int i = 0; i < 8; i++) {
        loq[i] = __fsub_rn(__fmul_rn(xq[i], cs[i]), __fmul_rn(yq[i], sn[i]));
        upq[i] = __fadd_rn(__fmul_rn(yq[i], cs[i]), __fmul_rn(xq[i], sn[i]));
        lok[i] = __fsub_rn(__fmul_rn(xk[i], cs[i]), __fmul_rn(yk[i], sn[i]));
        upk[i] = __fadd_rn(__fmul_rn(yk[i], cs[i]), __fmul_rn(xk[i], sn[i]));
    }

    // krot f32 (natural layout) for kquant
    *(float4*)&g_krot[rb + d0]      = *(float4*)&lok[0];
    *(float4*)&g_krot[rb + d0 + 4]  = *(float4*)&lok[4];
    *(float4*)&g_krot[rb + d0 + 64] = *(float4*)&upk[0];
    *(float4*)&g_krot[rb + d0 + 68] = *(float4*)&upk[4];

    // split planes (pre-swizzled chunks)
    size_t rowb = ((size_t)bh * SS + s) * 16;
    int pcl = c ^ (s & 7);
    int pcu = 8 + pcl;
    uint4 hi, lo;
    split8(loq, hi, lo); g_qh[rowb + pcl] = hi; g_ql[rowb + pcl] = lo;
    split8(upq, hi, lo); g_qh[rowb + pcu] = hi; g_ql[rowb + pcu] = lo;
    split8(lok, hi, lo); g_kh[rowb + pcl] = hi; g_kl[rowb + pcl] = lo;
    split8(upk, hi, lo); g_kh[rowb + pcu] = hi; g_kl[rowb + pcu] = lo;
}

// ---------------------------------------------------------------------------
// V split planes (no rope). One thread = one 8-elem chunk.
// ---------------------------------------------------------------------------
__global__ void v_split_kernel(const float* __restrict__ v) {
    int idx = blockIdx.x * 256 + threadIdx.x;
    if (idx >= BHN * SS * 16) return;
    int c = idx & 15;
    int s = (idx >> 4) & 2047;
    int bh = idx >> 15;
    size_t rb = ((size_t)bh * SS + s) * DD;
    float x[8];
    *(float4*)&x[0] = *(const float4*)&v[rb + c * 8];
    *(float4*)&x[4] = *(const float4*)&v[rb + c * 8 + 4];
    uint4 hi, lo;
    split8(x, hi, lo);
    size_t rowb = ((size_t)bh * SS + s) * 16;
    int pc = c ^ (s & 7);
    g_vh[rowb + pc] = hi;
    g_vl[rowb + pc] = lo;
}

// ---------------------------------------------------------------------------
// Flash attention via mma.sync m16n8k16 bf16 (3-pass split), no-rescale softmax.
// 8 warps, BM=128 (16 rows/warp), BN=64. P stays in registers (frag reuse).
// Smem: QH 0, QL 32K, KH 64K, KL 80K, VH 96K, VL 112K => 128KB.
// ---------------------------------------------------------------------------
#define SMQ_L 32768
#define SMK_H 65536
#define SMK_L 81920
#define SMV_H 98304
#define SMV_L 114688
#define SM_TOT 131072

__global__ __launch_bounds__(256, 1)
void attn_mma_kernel(const uint4* __restrict__ pqh, const uint4* __restrict__ pql,
                     const uint4* __restrict__ pkh, const uint4* __restrict__ pkl,
                     const uint4* __restrict__ pvh, const uint4* __restrict__ pvl,
                     float* __restrict__ out) {
    extern __shared__ char smc[];
    const int tid = threadIdx.x;
    const int w = tid >> 5, l = tid & 31;
    const int qb = 15 - (int)blockIdx.x;     // heavy blocks first
    const int bh = blockIdx.y;
    const uint32_t sb = smem_u32(smc);

    // Q tile copy (linear: planes are pre-swizzled)
    {
        size_t src = ((size_t)bh * SS + (size_t)qb * 128) * 16;
        uint4* dh = (uint4*)smc;
        uint4* dl = (uint4*)(smc + SMQ_L);
        for (int i = tid; i < 2048; i += 256) { dh[i] = pqh[src + i]; dl[i] = pql[src + i]; }
    }

    float o_[16][4];
    #pragma unroll
    for (int i = 0; i < 16; i++)
        #pragma unroll
        for (int j = 0; j < 4; j++) o_[i][j] = 0.0f;
    float lsum0 = 0.0f, lsum1 = 0.0f;

    const int rowmin = qb * 128 + w * 16;
    const int row0 = rowmin + (l >> 2);
    const int aR = ((l >> 3) & 1) * 8 + (l & 7);
    const int aK = ((l >> 4) & 1) * 8;
    const int bR = ((l >> 4) & 1) * 8 + (l & 7);
    const int bK = ((l >> 3) & 1) * 8;
    const float sc = 0.088388347648318447f * 1.4426950408889634f;  // 1/sqrt(128)*log2(e)

    const int nt = 2 * (qb + 1);
    for (int t = 0; t < nt; t++) {
        if (t) __syncthreads();
        {   // K/V tile copy (linear)
            size_t src = ((size_t)bh * SS + (size_t)t * 64) * 16;
            uint4* dkh = (uint4*)(smc + SMK_H);
            uint4* dkl = (uint4*)(smc + SMK_L);
            uint4* dvh = (uint4*)(smc + SMV_H);
            uint4* dvl = (uint4*)(smc + SMV_L);
            for (int i = tid; i < 1024; i += 256) {
                dkh[i] = pkh[src + i];
                dkl[i] = pkl[src + i];
                dvh[i] = pvh[src + i];
                dvl[i] = pvl[src + i];
            }
        }
        __syncthreads();
        if (64 * t > rowmin + 15) continue;   // whole tile above diagonal for this warp

        // ---- S = Qhi*Khi + Qlo*Khi + Qhi*Klo ----
        float s_[8][4];
        #pragma unroll
        for (int i = 0; i < 8; i++)
            #pragma unroll
            for (int j = 0; j < 4; j++) s_[i][j] = 0.0f;

        #pragma unroll
        for (int ks = 0; ks < 8; ks++) {
            uint32_t qh_[4], ql_[4];
            uint32_t aaddr = sb + soff(w * 16 + aR, ks * 16 + aK);
            LDSM4(qh_, aaddr);
            LDSM4(ql_, aaddr + SMQ_L);
            #pragma unroll
            for (int n0 = 0; n0 < 4; n0++) {
                uint32_t kh_[4], kl_[4];
                uint32_t baddr = sb + SMK_H + soff(n0 * 16 + bR, ks * 16 + bK);
                LDSM4(kh_, baddr);
                LDSM4(kl_, baddr + (SMK_L - SMK_H));
                MMA16816(s_[2*n0],   qh_[0],qh_[1],qh_[2],qh_[3], kh_[0], kh_[1]);
                MMA16816(s_[2*n0],   ql_[0],ql_[1],ql_[2],ql_[3], kh_[0], kh_[1]);
                MMA16816(s_[2*n0],   qh_[0],qh_[1],qh_[2],qh_[3], kl_[0], kl_[1]);
                MMA16816(s_[2*n0+1], qh_[0],qh_[1],qh_[2],qh_[3], kh_[2], kh_[3]);
                MMA16816(s_[2*n0+1], ql_[0],ql_[1],ql_[2],ql_[3], kh_[2], kh_[3]);
                MMA16816(s_[2*n0+1], qh_[0],qh_[1],qh_[2],qh_[3], kl_[2], kl_[3]);
            }
        }

        // ---- softmax (no rescale), build P fragments in regs ----
        const bool needmask = (64 * t + 63 > rowmin);
        uint32_t phi[8][2], plo[8][2];
        const int colb = 64 * t + 2 * (l & 3);
        #pragma unroll
        for (int n2 = 0; n2 < 8; n2++) {
            float p0 = ex2f(s_[n2][0] * sc);
            float p1 = ex2f(s_[n2][1] * sc);
            float p2 = ex2f(s_[n2][2] * sc);
            float p3 = ex2f(s_[n2][3] * sc);
            if (needmask) {
                int c0 = colb + 8 * n2;
                if (c0     > row0)     p0 = 0.0f;
                if (c0 + 1 > row0)     p1 = 0.0f;
                if (c0     > row0 + 8) p2 = 0.0f;
                if (c0 + 1 > row0 + 8) p3 = 0.0f;
            }
            lsum0 += p0 + p1;
            lsum1 += p2 + p3;
            uint32_t t0, t1;
            phi[n2][0] = bsplit2(p0, p1, t0); plo[n2][0] = t0;
            phi[n2][1] = bsplit2(p2, p3, t1); plo[n2][1] = t1;
        }

        // ---- O += Phi*Vhi + Plo*Vhi + Phi*Vlo ----
        const int vR = ((l >> 3) & 1) * 8 + (l & 7);
        const int vD = ((l >> 4) & 1) * 8;
        #pragma unroll
        for (int ks = 0; ks < 4; ks++) {
            uint32_t A0 = phi[2*ks][0], A1 = phi[2*ks][1];
            uint32_t A2 = phi[2*ks+1][0], A3 = phi[2*ks+1][1];
            uint32_t L0 = plo[2*ks][0], L1 = plo[2*ks][1];
            uint32_t L2 = plo[2*ks+1][0], L3 = plo[2*ks+1][1];
            #pragma unroll
            for (int d0 = 0; d0 < 8; d0++) {
                uint32_t vh_[4], vl_[4];
                uint32_t vaddr = sb + SMV_H + soff(ks * 16 + vR, d0 * 16 + vD);
                LDSM4T(vh_, vaddr);
                LDSM4T(vl_, vaddr + (SMV_L - SMV_H));
                MMA16816(o_[2*d0],   A0,A1,A2,A3, vh_[0], vh_[1]);
                MMA16816(o_[2*d0],   L0,L1,L2,L3, vh_[0], vh_[1]);
                MMA16816(o_[2*d0],   A0,A1,A2,A3, vl_[0], vl_[1]);
                MMA16816(o_[2*d0+1], A0,A1,A2,A3, vh_[2], vh_[3]);
                MMA16816(o_[2*d0+1], L0,L1,L2,L3, vh_[2], vh_[3]);
                MMA16816(o_[2*d0+1], A0,A1,A2,A3, vl_[2], vl_[3]);
            }
        }
    }

    // ---- epilogue: reduce l over quad, normalize, store ----
    lsum0 += __shfl_xor_sync(0xffffffffu, lsum0, 1);
    lsum0 += __shfl_xor_sync(0xffffffffu, lsum0, 2);
    lsum1 += __shfl_xor_sync(0xffffffffu, lsum1, 1);
    lsum1 += __shfl_xor_sync(0xffffffffu, lsum1, 2);
    float inv0 = 1.0f / lsum0;
    float inv1 = 1.0f / lsum1;
    size_t rbase = OFF_ATTN + ((size_t)bh * SS + row0) * DD;
    #pragma unroll
    for (int n2 = 0; n2 < 16; n2++) {
        int d = n2 * 8 + 2 * (l & 3);
        float2 a = {o_[n2][0] * inv0, o_[n2][1] * inv0};
        float2 b = {o_[n2][2] * inv1, o_[n2][3] * inv1};
        *(float2*)&out[rbase + d] = a;
        *(float2*)&out[rbase + 8 * DD + d] = b;
    }
}

// ---------------------------------------------------------------------------
// K side: per (b,h,d) channel, top-17 over seq (s>=4), abs desc / idx asc ties.
// ---------------------------------------------------------------------------
__global__ void kquant_kernel(const float* __restrict__ kr, float* __restrict__ out) {
    __shared__ unsigned mask[128 * 64];
    int bh = blockIdx.x;
    int d = threadIdx.x;
    const float* base = kr + (size_t)bh * SS * DD + d;

    float absv[17]; int idxs[17]; float vals[17];
    #pragma unroll
    for (int i = 0; i < 17; i++) { absv[i] = -1.0f; idxs[i] = 0; vals[i] = 0.0f; }

    for (int s = 4; s < SS; s++) {
        float vv = base[(size_t)s * DD];
        float a = fabsf(vv);
        if (a > absv[16]) {
            int p = 16;
            while (p > 0 && absv[p-1] < a) {
                absv[p] = absv[p-1]; idxs[p] = idxs[p-1]; vals[p] = vals[p-1];
                p--;
            }
            absv[p] = a; idxs[p] = s; vals[p] = vv;
        }
    }

    float absmax = absv[16];
    float scale = fmaxf(absmax, 1e-8f) / 127.0f;

    size_t sp = ((size_t)bh * DD + d) * 16;
    for (int i = 0; i < 16; i++) {
        out[OFF_KSPV + sp + i] = vals[i];
        out[OFF_KSPI + sp + i] = (float)idxs[i];
    }
    out[OFF_KSCALE + (size_t)bh * DD + d] = scale;

    unsigned* m = mask + d * 64;
    for (int wd = 0; wd < 64; wd++) m[wd] = 0u;
    for (int i = 0; i < 16; i++) m[idxs[i] >> 5] |= (1u << (idxs[i] & 31));

    float* qout = out + OFF_KQ + (size_t)bh * SS * DD + d;
    for (int s = 0; s < SS; s++) {
        float vv = base[(size_t)s * DD];
        float q;
        if (s < 4 || ((m[s >> 5] >> (s & 31)) & 1u)) {
            q = 0.0f;
        } else {
            q = rintf(vv / scale);
            q = fminf(fmaxf(q, -127.0f), 127.0f);
        }
        qout[(size_t)s * DD] = q;
    }
}

// ---------------------------------------------------------------------------
// V side: warp per token. top-5 of |v| over D=128 (abs desc, idx asc ties).
// ---------------------------------------------------------------------------
__global__ void vquant_kernel(const float* __restrict__ v, float* __restrict__ out) {
    int gwarp = (int)((blockIdx.x * (size_t)blockDim.x + threadIdx.x) >> 5);
    int lane = threadIdx.x & 31;
    if (gwarp >= BHN * SS) return;
    int s = gwarp & (SS - 1);

    const float* row = v + (size_t)gwarp * DD;
    float4 x = *(const float4*)(row + lane * 4);
    float vals[4] = {x.x, x.y, x.z, x.w};

    int tidx[4] = {0, 1, 2, 3};
    float tval[4] = {0.0f, 0.0f, 0.0f, 0.0f};
    float absmax = 0.0f;
    bool sink = (s < 4);

    if (!sink) {
        unsigned used = 0u;
        unsigned long long keys[4];
        #pragma unroll
        for (int i = 0; i < 4; i++) {
            unsigned ab = __float_as_uint(fabsf(vals[i]));
            keys[i] = ((unsigned long long)ab << 32) | (unsigned)(127 - (lane * 4 + i));
        }
        for (int rnd = 0; rnd < 5; rnd++) {
            unsigned long long best = 0ull;
            #pragma unroll
            for (int i = 0; i < 4; i++)
                if (!((used >> i) & 1u) && keys[i] > best) best = keys[i];
            #pragma unroll
            for (int off = 16; off >= 1; off >>= 1) {
                unsigned long long o2 = __shfl_xor_sync(0xffffffffu, best, off);
                if (o2 > best) best = o2;
            }
            int gidx = 127 - (int)(unsigned)(best & 0xffffffffull);
            float ab = __uint_as_float((unsigned)(best >> 32));
            int owner = gidx >> 2, slot = gidx & 3;
            if (lane == owner) used |= (1u << slot);
            if (rnd < 4) {
                float cand = (slot == 0) ? vals[0] : (slot == 1) ? vals[1]
                           : (slot == 2) ? vals[2] : vals[3];
                float sv = __shfl_sync(0xffffffffu, cand, owner);
                tidx[rnd] = gidx;
                tval[rnd] = sv;
            } else {
                absmax = ab;
            }
        }
    }

    float scale = fmaxf(absmax, 1e-8f) / 127.0f;

    float q[4];
    #pragma unroll
    for (int i = 0; i < 4; i++) {
        int gi = lane * 4 + i;
        bool zero = sink | (gi == tidx[0]) | (gi == tidx[1]) | (gi == tidx[2]) | (gi == tidx[3]);
        if (zero) {
            q[i] = 0.0f;
        } else {
            float r = rintf(vals[i] / scale);
            q[i] = fminf(fmaxf(r, -127.0f), 127.0f);
        }
    }
    float4 qo = {q[0], q[1], q[2], q[3]};
    *(float4*)&out[OFF_VQ + (size_t)gwarp * DD + lane * 4] = qo;

    if (lane == 0) {
        out[OFF_VSCALE + gwarp] = scale;
        #pragma unroll
        for (int t = 0; t < 4; t++) {
            out[OFF_VSPV + (size_t)gwarp * 4 + t] = tval[t];
            out[OFF_VSPI + (size_t)gwarp * 4 + t] = (float)tidx[t];
        }
    }
}

// ---------------------------------------------------------------------------
extern "C" void kernel_launch(void* const* d_in, const int* in_sizes, int n_in,
                              void* d_out, int out_size) {
    const float* q = (const float*)d_in[0];
    const float* k = (const float*)d_in[1];
    const float* v = (const float*)d_in[2];
    const int* pos = (const int*)d_in[3];
    float* out = (float*)d_out;

    float* krot; cudaGetSymbolAddress((void**)&krot, g_krot);
    uint4 *pqh, *pql, *pkh, *pkl, *pvh, *pvl;
    cudaGetSymbolAddress((void**)&pqh, g_qh);
    cudaGetSymbolAddress((void**)&pql, g_ql);
    cudaGetSymbolAddress((void**)&pkh, g_kh);
    cudaGetSymbolAddress((void**)&pkl, g_kl);
    cudaGetSymbolAddress((void**)&pvh, g_vh);
    cudaGetSymbolAddress((void**)&pvl, g_vl);

    // 1. inv_freq (64 double pows, bit-identical) then cos/sin table (cheap DP)
    invf_kernel<<<1, 64>>>();
    table_kernel<<<SS, 64>>>();

    // 2. Fused RoPE + bf16 split planes (Q, K) + krot f32
    rope_split_kernel<<<(BHN * SS * 8 + 255) / 256, 256>>>(q, k, pos);

    // 3. V split planes
    v_split_kernel<<<(BHN * SS * 16 + 255) / 256, 256>>>(v);

    // 4. Attention (mma.sync bf16, 3-pass split)
    {
        cudaFuncSetAttribute(attn_mma_kernel, cudaFuncAttributeMaxDynamicSharedMemorySize, SM_TOT);
        dim3 grid(16, BHN);
        attn_mma_kernel<<<grid, 256, SM_TOT>>>(pqh, pql, pkh, pkl, pvh, pvl, out);
    }

    // 5. K quant + outliers
    kquant_kernel<<<BHN, 128>>>(krot, out);

    // 6. V quant + outliers
    {
        int warps = BHN * SS;
        int threads = 256;
        int blocks = (warps * 32 + threads - 1) / threads;
        vquant_kernel<<<blocks, threads>>>(v, out);
    }
}

// round 10
// speedup vs baseline: 5.3285x; 5.3285x over previous
#include <cuda_runtime.h>
#include <cuda_bf16.h>
#include <math.h>
#include <stdint.h>

// Problem dims
#define BB 2
#define HH 32
#define SS 2048
#define DD 128
#define BHN (BB*HH)

// Output layout (floats), concatenated in reference return order
#define OFF_ATTN   ((size_t)0)
#define OFF_KQ     ((size_t)16777216)
#define OFF_KSCALE ((size_t)33554432)
#define OFF_VQ     ((size_t)33562624)
#define OFF_VSCALE ((size_t)50339840)
#define OFF_KSPV   ((size_t)50470912)
#define OFF_KSPI   ((size_t)50601984)
#define OFF_VSPV   ((size_t)50733056)
#define OFF_VSPI   ((size_t)51257344)

// Scratch (device globals: no allocation allowed)
__device__ float g_krot[BB*HH*SS*DD];
__device__ float g_invf[64];
__device__ float g_cos[SS*64];
__device__ float g_sin[SS*64];
// Split-bf16 planes, pre-swizzled rows of 256B (16 x 16B chunks, chunk ^= row&7)
__device__ uint4 g_qh[BHN*SS*16];
__device__ uint4 g_ql[BHN*SS*16];
__device__ uint4 g_kh[BHN*SS*16];
__device__ uint4 g_kl[BHN*SS*16];
__device__ uint4 g_vh[BHN*SS*16];
__device__ uint4 g_vl[BHN*SS*16];
// K top-k pipeline scratch
__device__ unsigned long long g_pk[BHN*DD*16*17];   // partial top-17 keys
__device__ unsigned g_mask[BHN*64*DD];              // outlier bitmap [bh][w][d]

// ===========================================================================
// helpers
// ===========================================================================
__device__ __forceinline__ uint32_t smem_u32(const void* p) {
    uint32_t a;
    asm("{ .reg .u64 t; cvta.to.shared.u64 t, %1; cvt.u32.u64 %0, t; }"
        : "=r"(a) : "l"(p));
    return a;
}

// swizzled byte offset within a [rows][128 bf16] tile, 256B row pitch
__device__ __forceinline__ int soff(int r, int d) {
    return r * 256 + ((((d >> 3) ^ (r & 7)) & 15) << 4) + ((d & 7) << 1);
}

#define LDSM4(r, a) \
    asm volatile("ldmatrix.sync.aligned.m8n8.x4.shared.b16 {%0,%1,%2,%3}, [%4];" \
        : "=r"((r)[0]), "=r"((r)[1]), "=r"((r)[2]), "=r"((r)[3]) : "r"(a))
#define LDSM4T(r, a) \
    asm volatile("ldmatrix.sync.aligned.m8n8.x4.trans.shared.b16 {%0,%1,%2,%3}, [%4];" \
        : "=r"((r)[0]), "=r"((r)[1]), "=r"((r)[2]), "=r"((r)[3]) : "r"(a))

#define MMA16816(c, a0,a1,a2,a3, b0,b1) \
    asm volatile("mma.sync.aligned.m16n8k16.row.col.f32.bf16.bf16.f32 " \
        "{%0,%1,%2,%3}, {%4,%5,%6,%7}, {%8,%9}, {%0,%1,%2,%3};" \
        : "+f"((c)[0]), "+f"((c)[1]), "+f"((c)[2]), "+f"((c)[3]) \
        : "r"(a0), "r"(a1), "r"(a2), "r"(a3), "r"(b0), "r"(b1))

__device__ __forceinline__ float ex2f(float x) {
    float y;
    asm("ex2.approx.f32 %0, %1;" : "=f"(y) : "f"(x));
    return y;
}

// bf16 split: hi = bf16(a,b), lo = bf16(residuals). hi low half = a.
__device__ __forceinline__ uint32_t bsplit2(float a, float b, uint32_t& lo) {
    __nv_bfloat16 ha = __float2bfloat16_rn(a);
    __nv_bfloat16 hb = __float2bfloat16_rn(b);
    float ra = a - __bfloat162float(ha);
    float rb = b - __bfloat162float(hb);
    __nv_bfloat16 la = __float2bfloat16_rn(ra);
    __nv_bfloat16 lb = __float2bfloat16_rn(rb);
    lo = ((uint32_t)__bfloat16_as_ushort(lb) << 16) | (uint32_t)__bfloat16_as_ushort(la);
    return ((uint32_t)__bfloat16_as_ushort(hb) << 16) | (uint32_t)__bfloat16_as_ushort(ha);
}

__device__ __forceinline__ void split8(const float* v, uint4& hi, uint4& lo) {
    uint32_t l0, l1, l2, l3;
    hi.x = bsplit2(v[0], v[1], l0);
    hi.y = bsplit2(v[2], v[3], l1);
    hi.z = bsplit2(v[4], v[5], l2);
    hi.w = bsplit2(v[6], v[7], l3);
    lo.x = l0; lo.y = l1; lo.z = l2; lo.w = l3;
}

// Register-resident guarded top-17 insert (descending u64 keys, all static idx).
__device__ __forceinline__ void ins17(unsigned long long* a, unsigned long long key) {
    if (key > a[16]) {
        #pragma unroll
        for (int j = 16; j > 0; j--) {
            unsigned long long pj = a[j-1];
            a[j] = (key > pj) ? pj : ((key > a[j]) ? key : a[j]);
        }
        if (key > a[0]) a[0] = key;
    }
}

// ---------------------------------------------------------------------------
// inv_freq: 64 double pow calls only (bit-identical to reference).
// ---------------------------------------------------------------------------
__global__ void invf_kernel() {
    int j = threadIdx.x;
    double e = (double)(2 * j) / 128.0;
    double p = pow(10000.0, e);
    float pf = (float)p;
    g_invf[j] = 1.0f / pf;
}

// ---------------------------------------------------------------------------
// Custom double sincos (Cody-Waite + fdlibm polys); bit-matches libm at f32.
// ---------------------------------------------------------------------------
__device__ __forceinline__ void dsincos_f(float angf, float* cs, float* sn) {
    const double pio2_1  = 1.57079632673412561417e+00;
    const double pio2_1t = 6.07710050650619224932e-11;
    double x = (double)angf;
    double kd = rint(x * 6.36619772367581382433e-01);
    double r = x - kd * pio2_1;
    r = r - kd * pio2_1t;
    double z = r * r;
    double ps = 1.58969099521155010221e-10;
    ps = ps * z + -2.50507602534068634195e-08;
    ps = ps * z +  2.75573137070700676789e-06;
    ps = ps * z + -1.98412698298579493134e-04;
    ps = ps * z +  8.33333333332248946124e-03;
    ps = ps * z + -1.66666666666666324348e-01;
    double s = r + r * z * ps;
    double pc = -1.13596475577881948265e-11;
    pc = pc * z +  2.08757232129817482790e-09;
    pc = pc * z + -2.75573143513906633035e-07;
    pc = pc * z +  2.48015872894767294178e-05;
    pc = pc * z + -1.38888888888741095749e-03;
    pc = pc * z +  4.16666666666666019037e-02;
    double c = 1.0 + z * (-0.5 + z * pc);
    int q = ((int)kd) & 3;
    double sv, cv;
    if (q == 0)      { sv = s;  cv = c;  }
    else if (q == 1) { sv = c;  cv = -s; }
    else if (q == 2) { sv = -s; cv = -c; }
    else             { sv = -c; cv = s;  }
    *sn = (float)sv;
    *cs = (float)cv;
}

__global__ void table_kernel() {
    int s = blockIdx.x;
    int j = threadIdx.x;
    float ang = __fmul_rn((float)s, g_invf[j]);
    float c, sn;
    dsincos_f(ang, &c, &sn);
    g_cos[s * 64 + j] = c;
    g_sin[s * 64 + j] = sn;
}

// ---------------------------------------------------------------------------
// Fused RoPE + split-bf16 planes + krot f32.
// ---------------------------------------------------------------------------
__global__ void rope_split_kernel(const float* __restrict__ q, const float* __restrict__ k,
                                  const int* __restrict__ pos_ids) {
    int idx = blockIdx.x * 256 + threadIdx.x;
    if (idx >= BHN * SS * 8) return;
    int c = idx & 7;
    int s = (idx >> 3) & 2047;
    int bh = idx >> 14;
    int b = bh >> 5;
    int pos = pos_ids[b * SS + s];
    int d0 = c * 8;
    size_t rb = ((size_t)bh * SS + s) * DD;

    float xq[8], yq[8], xk[8], yk[8], cs[8], sn[8];
    *(float4*)&xq[0] = *(const float4*)&q[rb + d0];
    *(float4*)&xq[4] = *(const float4*)&q[rb + d0 + 4];
    *(float4*)&yq[0] = *(const float4*)&q[rb + d0 + 64];
    *(float4*)&yq[4] = *(const float4*)&q[rb + d0 + 68];
    *(float4*)&xk[0] = *(const float4*)&k[rb + d0];
    *(float4*)&xk[4] = *(const float4*)&k[rb + d0 + 4];
    *(float4*)&yk[0] = *(const float4*)&k[rb + d0 + 64];
    *(float4*)&yk[4] = *(const float4*)&k[rb + d0 + 68];
    #pragma unroll
    for (int i = 0; i < 8; i++) {
        cs[i] = g_cos[pos * 64 + d0 + i];
        sn[i] = g_sin[pos * 64 + d0 + i];
    }

    float loq[8], upq[8], lok[8], upk[8];
    #pragma unroll
    for (int i = 0; i < 8; i++) {
        loq[i] = __fsub_rn(__fmul_rn(xq[i], cs[i]), __fmul_rn(yq[i], sn[i]));
        upq[i] = __fadd_rn(__fmul_rn(yq[i], cs[i]), __fmul_rn(xq[i], sn[i]));
        lok[i] = __fsub_rn(__fmul_rn(xk[i], cs[i]), __fmul_rn(yk[i], sn[i]));
        upk[i] = __fadd_rn(__fmul_rn(yk[i], cs[i]), __fmul_rn(xk[i], sn[i]));
    }

    *(float4*)&g_krot[rb + d0]      = *(float4*)&lok[0];
    *(float4*)&g_krot[rb + d0 + 4]  = *(float4*)&lok[4];
    *(float4*)&g_krot[rb + d0 + 64] = *(float4*)&upk[0];
    *(float4*)&g_krot[rb + d0 + 68] = *(float4*)&upk[4];

    size_t rowb = ((size_t)bh * SS + s) * 16;
    int pcl = c ^ (s & 7);
    int pcu = 8 + pcl;
    uint4 hi, lo;
    split8(loq, hi, lo); g_qh[rowb + pcl] = hi; g_ql[rowb + pcl] = lo;
    split8(upq, hi, lo); g_qh[rowb + pcu] = hi; g_ql[rowb + pcu] = lo;
    split8(lok, hi, lo); g_kh[rowb + pcl] = hi; g_kl[rowb + pcl] = lo;
    split8(upk, hi, lo); g_kh[rowb + pcu] = hi; g_kl[rowb + pcu] = lo;
}

// ---------------------------------------------------------------------------
// V split planes.
// ---------------------------------------------------------------------------
__global__ void v_split_kernel(const float* __restrict__ v) {
    int idx = blockIdx.x * 256 + threadIdx.x;
    if (idx >= BHN * SS * 16) return;
    int c = idx & 15;
    int s = (idx >> 4) & 2047;
    int bh = idx >> 15;
    size_t rb = ((size_t)bh * SS + s) * DD;
    float x[8];
    *(float4*)&x[0] = *(const float4*)&v[rb + c * 8];
    *(float4*)&x[4] = *(const float4*)&v[rb + c * 8 + 4];
    uint4 hi, lo;
    split8(x, hi, lo);
    size_t rowb = ((size_t)bh * SS + s) * 16;
    int pc = c ^ (s & 7);
    g_vh[rowb + pc] = hi;
    g_vl[rowb + pc] = lo;
}

// ---------------------------------------------------------------------------
// Flash attention via mma.sync m16n8k16 bf16 (3-pass split), no-rescale softmax.
// ---------------------------------------------------------------------------
#define SMQ_L 32768
#define SMK_H 65536
#define SMK_L 81920
#define SMV_H 98304
#define SMV_L 114688
#define SM_TOT 131072

__global__ __launch_bounds__(256, 1)
void attn_mma_kernel(const uint4* __restrict__ pqh, const uint4* __restrict__ pql,
                     const uint4* __restrict__ pkh, const uint4* __restrict__ pkl,
                     const uint4* __restrict__ pvh, const uint4* __restrict__ pvl,
                     float* __restrict__ out) {
    extern __shared__ char smc[];
    const int tid = threadIdx.x;
    const int w = tid >> 5, l = tid & 31;
    const int qb = 15 - (int)blockIdx.x;     // heavy blocks first
    const int bh = blockIdx.y;
    const uint32_t sb = smem_u32(smc);

    {
        size_t src = ((size_t)bh * SS + (size_t)qb * 128) * 16;
        uint4* dh = (uint4*)smc;
        uint4* dl = (uint4*)(smc + SMQ_L);
        for (int i = tid; i < 2048; i += 256) { dh[i] = pqh[src + i]; dl[i] = pql[src + i]; }
    }

    float o_[16][4];
    #pragma unroll
    for (int i = 0; i < 16; i++)
        #pragma unroll
        for (int j = 0; j < 4; j++) o_[i][j] = 0.0f;
    float lsum0 = 0.0f, lsum1 = 0.0f;

    const int rowmin = qb * 128 + w * 16;
    const int row0 = rowmin + (l >> 2);
    const int aR = ((l >> 3) & 1) * 8 + (l & 7);
    const int aK = ((l >> 4) & 1) * 8;
    const int bR = ((l >> 4) & 1) * 8 + (l & 7);
    const int bK = ((l >> 3) & 1) * 8;
    const float sc = 0.088388347648318447f * 1.4426950408889634f;

    const int nt = 2 * (qb + 1);
    for (int t = 0; t < nt; t++) {
        if (t) __syncthreads();
        {
            size_t src = ((size_t)bh * SS + (size_t)t * 64) * 16;
            uint4* dkh = (uint4*)(smc + SMK_H);
            uint4* dkl = (uint4*)(smc + SMK_L);
            uint4* dvh = (uint4*)(smc + SMV_H);
            uint4* dvl = (uint4*)(smc + SMV_L);
            for (int i = tid; i < 1024; i += 256) {
                dkh[i] = pkh[src + i];
                dkl[i] = pkl[src + i];
                dvh[i] = pvh[src + i];
                dvl[i] = pvl[src + i];
            }
        }
        __syncthreads();
        if (64 * t > rowmin + 15) continue;

        float s_[8][4];
        #pragma unroll
        for (int i = 0; i < 8; i++)
            #pragma unroll
            for (int j = 0; j < 4; j++) s_[i][j] = 0.0f;

        #pragma unroll
        for (int ks = 0; ks < 8; ks++) {
            uint32_t qh_[4], ql_[4];
            uint32_t aaddr = sb + soff(w * 16 + aR, ks * 16 + aK);
            LDSM4(qh_, aaddr);
            LDSM4(ql_, aaddr + SMQ_L);
            #pragma unroll
            for (int n0 = 0; n0 < 4; n0++) {
                uint32_t kh_[4], kl_[4];
                uint32_t baddr = sb + SMK_H + soff(n0 * 16 + bR, ks * 16 + bK);
                LDSM4(kh_, baddr);
                LDSM4(kl_, baddr + (SMK_L - SMK_H));
                MMA16816(s_[2*n0],   qh_[0],qh_[1],qh_[2],qh_[3], kh_[0], kh_[1]);
                MMA16816(s_[2*n0],   ql_[0],ql_[1],ql_[2],ql_[3], kh_[0], kh_[1]);
                MMA16816(s_[2*n0],   qh_[0],qh_[1],qh_[2],qh_[3], kl_[0], kl_[1]);
                MMA16816(s_[2*n0+1], qh_[0],qh_[1],qh_[2],qh_[3], kh_[2], kh_[3]);
                MMA16816(s_[2*n0+1], ql_[0],ql_[1],ql_[2],ql_[3], kh_[2], kh_[3]);
                MMA16816(s_[2*n0+1], qh_[0],qh_[1],qh_[2],qh_[3], kl_[2], kl_[3]);
            }
        }

        const bool needmask = (64 * t + 63 > rowmin);
        uint32_t phi[8][2], plo[8][2];
        const int colb = 64 * t + 2 * (l & 3);
        #pragma unroll
        for (int n2 = 0; n2 < 8; n2++) {
            float p0 = ex2f(s_[n2][0] * sc);
            float p1 = ex2f(s_[n2][1] * sc);
            float p2 = ex2f(s_[n2][2] * sc);
            float p3 = ex2f(s_[n2][3] * sc);
            if (needmask) {
                int c0 = colb + 8 * n2;
                if (c0     > row0)     p0 = 0.0f;
                if (c0 + 1 > row0)     p1 = 0.0f;
                if (c0     > row0 + 8) p2 = 0.0f;
                if (c0 + 1 > row0 + 8) p3 = 0.0f;
            }
            lsum0 += p0 + p1;
            lsum1 += p2 + p3;
            uint32_t t0, t1;
            phi[n2][0] = bsplit2(p0, p1, t0); plo[n2][0] = t0;
            phi[n2][1] = bsplit2(p2, p3, t1); plo[n2][1] = t1;
        }

        #pragma unroll
        for (int ks = 0; ks < 4; ks++) {
            uint32_t A0 = phi[2*ks][0], A1 = phi[2*ks][1];
            uint32_t A2 = phi[2*ks+1][0], A3 = phi[2*ks+1][1];
            uint32_t L0 = plo[2*ks][0], L1 = plo[2*ks][1];
            uint32_t L2 = plo[2*ks+1][0], L3 = plo[2*ks+1][1];
            #pragma unroll
            for (int d0 = 0; d0 < 8; d0++) {
                uint32_t vh_[4], vl_[4];
                uint32_t vaddr = sb + SMV_H + soff(ks * 16 + ((l >> 3) & 1) * 8 + (l & 7), d0 * 16 + ((l >> 4) & 1) * 8);
                LDSM4T(vh_, vaddr);
                LDSM4T(vl_, vaddr + (SMV_L - SMV_H));
                MMA16816(o_[2*d0],   A0,A1,A2,A3, vh_[0], vh_[1]);
                MMA16816(o_[2*d0],   L0,L1,L2,L3, vh_[0], vh_[1]);
                MMA16816(o_[2*d0],   A0,A1,A2,A3, vl_[0], vl_[1]);
                MMA16816(o_[2*d0+1], A0,A1,A2,A3, vh_[2], vh_[3]);
                MMA16816(o_[2*d0+1], L0,L1,L2,L3, vh_[2], vh_[3]);
                MMA16816(o_[2*d0+1], A0,A1,A2,A3, vl_[2], vl_[3]);
            }
        }
    }

    lsum0 += __shfl_xor_sync(0xffffffffu, lsum0, 1);
    lsum0 += __shfl_xor_sync(0xffffffffu, lsum0, 2);
    lsum1 += __shfl_xor_sync(0xffffffffu, lsum1, 1);
    lsum1 += __shfl_xor_sync(0xffffffffu, lsum1, 2);
    float inv0 = 1.0f / lsum0;
    float inv1 = 1.0f / lsum1;
    size_t rbase = OFF_ATTN + ((size_t)bh * SS + row0) * DD;
    #pragma unroll
    for (int n2 = 0; n2 < 16; n2++) {
        int d = n2 * 8 + 2 * (l & 3);
        float2 a = {o_[n2][0] * inv0, o_[n2][1] * inv0};
        float2 b = {o_[n2][2] * inv1, o_[n2][3] * inv1};
        *(float2*)&out[rbase + d] = a;
        *(float2*)&out[rbase + 8 * DD + d] = b;
    }
}

// ---------------------------------------------------------------------------
// K top-k pipeline. Keys = (abs_bits << 32) | (4095 - s): abs desc, idx asc.
// ---------------------------------------------------------------------------
// Stage 1: per-(bh, s-chunk of 128, d) partial top-17, registers only.
__global__ void kq_partial(const float* __restrict__ kr) {
    int bh = blockIdx.x, ch = blockIdx.y, d = threadIdx.x;
    unsigned long long a[17];
    #pragma unroll
    for (int i = 0; i < 17; i++) a[i] = 0ull;

    int s0 = ch * 128;
    const float* p = kr + ((size_t)bh * SS + s0) * DD + d;
    int ibeg = (ch == 0) ? 4 : 0;
    for (int i = ibeg; i < 128; i++) {
        float v = p[(size_t)i * DD];
        unsigned ab = __float_as_uint(fabsf(v));
        unsigned long long key = ((unsigned long long)ab << 32) | (unsigned)(4095 - (s0 + i));
        ins17(a, key);
    }
    unsigned long long* dst = g_pk + (((size_t)bh * DD + d) * 16 + ch) * 17;
    #pragma unroll
    for (int i = 0; i < 17; i++) dst[i] = a[i];
}

// Stage 2: merge 16 partials -> exact top-17; emit scale, sp outputs, bitmap.
__global__ void kq_merge(const float* __restrict__ kr, float* __restrict__ out) {
    int bh = blockIdx.x, d = threadIdx.x;
    unsigned long long a[17];
    #pragma unroll
    for (int i = 0; i < 17; i++) a[i] = 0ull;

    const unsigned long long* pk = g_pk + ((size_t)bh * DD + d) * 16 * 17;
    for (int t = 0; t < 16 * 17; t++) ins17(a, pk[t]);

    float absmax = __uint_as_float((unsigned)(a[16] >> 32));
    float scale = fmaxf(absmax, 1e-8f) / 127.0f;
    out[OFF_KSCALE + (size_t)bh * DD + d] = scale;

    size_t sp = ((size_t)bh * DD + d) * 16;
    int idxs[16];
    #pragma unroll
    for (int i = 0; i < 16; i++) {
        int s = 4095 - (int)(unsigned)(a[i] & 0xFFFFFFFFull);
        idxs[i] = s;
        out[OFF_KSPI + sp + i] = (float)s;
        out[OFF_KSPV + sp + i] = kr[((size_t)bh * SS + s) * DD + d];
    }

    unsigned m[64];
    for (int w = 0; w < 64; w++) m[w] = 0u;
    #pragma unroll
    for (int i = 0; i < 16; i++) m[idxs[i] >> 5] |= (1u << (idxs[i] & 31));
    for (int w = 0; w < 64; w++)
        g_mask[((size_t)bh * 64 + w) * DD + d] = m[w];
}

// Stage 3: fully parallel quantize with bitmap + scales in smem.
__global__ __launch_bounds__(256)
void kq_write(const float* __restrict__ kr, float* __restrict__ out) {
    __shared__ unsigned smask[512];   // [w4 0..3][d 0..127]
    __shared__ float sscale[128];
    int bh = blockIdx.x, scn = blockIdx.y;
    int tid = threadIdx.x;

    for (int i = tid; i < 512; i += 256) {
        int w4 = i >> 7, d = i & 127;
        smask[i] = g_mask[((size_t)bh * 64 + scn * 4 + w4) * DD + d];
    }
    if (tid < 128) sscale[tid] = out[OFF_KSCALE + (size_t)bh * DD + tid];
    __syncthreads();

    for (int u = tid; u < 4096; u += 256) {
        int r = u >> 5, d4 = u & 31;
        int s = scn * 128 + r;
        size_t off = ((size_t)bh * SS + s) * DD + d4 * 4;
        float4 v = *(const float4*)(kr + off);
        int w4 = r >> 5;
        int bit = s & 31;
        float vv[4] = {v.x, v.y, v.z, v.w};
        float q[4];
        #pragma unroll
        for (int j = 0; j < 4; j++) {
            int dd = d4 * 4 + j;
            bool z = (s < 4) || ((smask[w4 * 128 + dd] >> bit) & 1u);
            if (z) {
                q[j] = 0.0f;
            } else {
                float r2 = rintf(vv[j] / sscale[dd]);
                q[j] = fminf(fmaxf(r2, -127.0f), 127.0f);
            }
        }
        float4 qo = {q[0], q[1], q[2], q[3]};
        *(float4*)&out[OFF_KQ + off] = qo;
    }
}

// ---------------------------------------------------------------------------
// V side: warp per token. top-5 of |v| over D=128 (abs desc, idx asc ties).
// ---------------------------------------------------------------------------
__global__ void vquant_kernel(const float* __restrict__ v, float* __restrict__ out) {
    int gwarp = (int)((blockIdx.x * (size_t)blockDim.x + threadIdx.x) >> 5);
    int lane = threadIdx.x & 31;
    if (gwarp >= BHN * SS) return;
    int s = gwarp & (SS - 1);

    const float* row = v + (size_t)gwarp * DD;
    float4 x = *(const float4*)(row + lane * 4);
    float vals[4] = {x.x, x.y, x.z, x.w};

    int tidx[4] = {0, 1, 2, 3};
    float tval[4] = {0.0f, 0.0f, 0.0f, 0.0f};
    float absmax = 0.0f;
    bool sink = (s < 4);

    if (!sink) {
        unsigned used = 0u;
        unsigned long long keys[4];
        #pragma unroll
        for (int i = 0; i < 4; i++) {
            unsigned ab = __float_as_uint(fabsf(vals[i]));
            keys[i] = ((unsigned long long)ab << 32) | (unsigned)(127 - (lane * 4 + i));
        }
        for (int rnd = 0; rnd < 5; rnd++) {
            unsigned long long best = 0ull;
            #pragma unroll
            for (int i = 0; i < 4; i++)
                if (!((used >> i) & 1u) && keys[i] > best) best = keys[i];
            #pragma unroll
            for (int off = 16; off >= 1; off >>= 1) {
                unsigned long long o2 = __shfl_xor_sync(0xffffffffu, best, off);
                if (o2 > best) best = o2;
            }
            int gidx = 127 - (int)(unsigned)(best & 0xffffffffull);
            float ab = __uint_as_float((unsigned)(best >> 32));
            int owner = gidx >> 2, slot = gidx & 3;
            if (lane == owner) used |= (1u << slot);
            if (rnd < 4) {
                float cand = (slot == 0) ? vals[0] : (slot == 1) ? vals[1]
                           : (slot == 2) ? vals[2] : vals[3];
                float sv = __shfl_sync(0xffffffffu, cand, owner);
                tidx[rnd] = gidx;
                tval[rnd] = sv;
            } else {
                absmax = ab;
            }
        }
    }

    float scale = fmaxf(absmax, 1e-8f) / 127.0f;

    float q[4];
    #pragma unroll
    for (int i = 0; i < 4; i++) {
        int gi = lane * 4 + i;
        bool zero = sink | (gi == tidx[0]) | (gi == tidx[1]) | (gi == tidx[2]) | (gi == tidx[3]);
        if (zero) {
            q[i] = 0.0f;
        } else {
            float r = rintf(vals[i] / scale);
            q[i] = fminf(fmaxf(r, -127.0f), 127.0f);
        }
    }
    float4 qo = {q[0], q[1], q[2], q[3]};
    *(float4*)&out[OFF_VQ + (size_t)gwarp * DD + lane * 4] = qo;

    if (lane == 0) {
        out[OFF_VSCALE + gwarp] = scale;
        #pragma unroll
        for (int t = 0; t < 4; t++) {
            out[OFF_VSPV + (size_t)gwarp * 4 + t] = tval[t];
            out[OFF_VSPI + (size_t)gwarp * 4 + t] = (float)tidx[t];
        }
    }
}

// ---------------------------------------------------------------------------
extern "C" void kernel_launch(void* const* d_in, const int* in_sizes, int n_in,
                              void* d_out, int out_size) {
    const float* q = (const float*)d_in[0];
    const float* k = (const float*)d_in[1];
    const float* v = (const float*)d_in[2];
    const int* pos = (const int*)d_in[3];
    float* out = (float*)d_out;

    float* krot; cudaGetSymbolAddress((void**)&krot, g_krot);
    uint4 *pqh, *pql, *pkh, *pkl, *pvh, *pvl;
    cudaGetSymbolAddress((void**)&pqh, g_qh);
    cudaGetSymbolAddress((void**)&pql, g_ql);
    cudaGetSymbolAddress((void**)&pkh, g_kh);
    cudaGetSymbolAddress((void**)&pkl, g_kl);
    cudaGetSymbolAddress((void**)&pvh, g_vh);
    cudaGetSymbolAddress((void**)&pvl, g_vl);

    // 1. inv_freq + cos/sin table
    invf_kernel<<<1, 64>>>();
    table_kernel<<<SS, 64>>>();

    // 2. Fused RoPE + bf16 split planes (Q, K) + krot f32
    rope_split_kernel<<<(BHN * SS * 8 + 255) / 256, 256>>>(q, k, pos);

    // 3. V split planes
    v_split_kernel<<<(BHN * SS * 16 + 255) / 256, 256>>>(v);

    // 4. Attention (mma.sync bf16, 3-pass split)
    {
        cudaFuncSetAttribute(attn_mma_kernel, cudaFuncAttributeMaxDynamicSharedMemorySize, SM_TOT);
        dim3 grid(16, BHN);
        attn_mma_kernel<<<grid, 256, SM_TOT>>>(pqh, pql, pkh, pkl, pvh, pvl, out);
    }

    // 5. K quant pipeline: partial top-17 -> merge -> quantize
    {
        dim3 gp(BHN, 16);
        kq_partial<<<gp, 128>>>(krot);
        kq_merge<<<BHN, 128>>>(krot, out);
        dim3 gw(BHN, 16);
        kq_write<<<gw, 256>>>(krot, out);
    }

    // 6. V quant + outliers
    {
        int warps = BHN * SS;
        int threads = 256;
        int blocks = (warps * 32 + threads - 1) / threads;
        vquant_kernel<<<blocks, threads>>>(v, out);
    }
}

// round 11
// speedup vs baseline: 6.9259x; 1.2998x over previous
#include <cuda_runtime.h>
#include <cuda_bf16.h>
#include <math.h>
#include <stdint.h>

// Problem dims
#define BB 2
#define HH 32
#define SS 2048
#define DD 128
#define BHN (BB*HH)

// Output layout (floats), concatenated in reference return order
#define OFF_ATTN   ((size_t)0)
#define OFF_KQ     ((size_t)16777216)
#define OFF_KSCALE ((size_t)33554432)
#define OFF_VQ     ((size_t)33562624)
#define OFF_VSCALE ((size_t)50339840)
#define OFF_KSPV   ((size_t)50470912)
#define OFF_KSPI   ((size_t)50601984)
#define OFF_VSPV   ((size_t)50733056)
#define OFF_VSPI   ((size_t)51257344)

// Scratch (device globals: no allocation allowed)
__device__ float g_krot[BB*HH*SS*DD];
__device__ float g_invf[64];
__device__ float g_cos[SS*64];
__device__ float g_sin[SS*64];
// Split-bf16 planes, pre-swizzled rows of 256B (16 x 16B chunks, chunk ^= row&7)
__device__ uint4 g_qh[BHN*SS*16];
__device__ uint4 g_ql[BHN*SS*16];
__device__ uint4 g_kh[BHN*SS*16];
__device__ uint4 g_kl[BHN*SS*16];
__device__ uint4 g_vh[BHN*SS*16];
__device__ uint4 g_vl[BHN*SS*16];
// K top-k pipeline scratch
__device__ unsigned long long g_pk[BHN*DD*16*17];   // partial top-17 keys
__device__ unsigned g_mask[BHN*64*DD];              // outlier bitmap [bh][w][d]

// ===========================================================================
// helpers
// ===========================================================================
__device__ __forceinline__ uint32_t smem_u32(const void* p) {
    uint32_t a;
    asm("{ .reg .u64 t; cvta.to.shared.u64 t, %1; cvt.u32.u64 %0, t; }"
        : "=r"(a) : "l"(p));
    return a;
}

// swizzled byte offset within a [rows][128 bf16] tile, 256B row pitch
__device__ __forceinline__ int soff(int r, int d) {
    return r * 256 + ((((d >> 3) ^ (r & 7)) & 15) << 4) + ((d & 7) << 1);
}

#define LDSM4(r, a) \
    asm volatile("ldmatrix.sync.aligned.m8n8.x4.shared.b16 {%0,%1,%2,%3}, [%4];" \
        : "=r"((r)[0]), "=r"((r)[1]), "=r"((r)[2]), "=r"((r)[3]) : "r"(a))
#define LDSM4T(r, a) \
    asm volatile("ldmatrix.sync.aligned.m8n8.x4.trans.shared.b16 {%0,%1,%2,%3}, [%4];" \
        : "=r"((r)[0]), "=r"((r)[1]), "=r"((r)[2]), "=r"((r)[3]) : "r"(a))

#define MMA16816(c, a0,a1,a2,a3, b0,b1) \
    asm volatile("mma.sync.aligned.m16n8k16.row.col.f32.bf16.bf16.f32 " \
        "{%0,%1,%2,%3}, {%4,%5,%6,%7}, {%8,%9}, {%0,%1,%2,%3};" \
        : "+f"((c)[0]), "+f"((c)[1]), "+f"((c)[2]), "+f"((c)[3]) \
        : "r"(a0), "r"(a1), "r"(a2), "r"(a3), "r"(b0), "r"(b1))

#define CP_ASYNC16(dst, src) \
    asm volatile("cp.async.cg.shared.global [%0], [%1], 16;" \
        :: "r"(dst), "l"(src) : "memory")
#define CP_COMMIT() asm volatile("cp.async.commit_group;" ::: "memory")
#define CP_WAIT0()  asm volatile("cp.async.wait_group 0;" ::: "memory")
#define CP_WAIT1()  asm volatile("cp.async.wait_group 1;" ::: "memory")

__device__ __forceinline__ float ex2f(float x) {
    float y;
    asm("ex2.approx.f32 %0, %1;" : "=f"(y) : "f"(x));
    return y;
}

// bf16 split: hi = bf16(a,b), lo = bf16(residuals). hi low half = a.
__device__ __forceinline__ uint32_t bsplit2(float a, float b, uint32_t& lo) {
    __nv_bfloat16 ha = __float2bfloat16_rn(a);
    __nv_bfloat16 hb = __float2bfloat16_rn(b);
    float ra = a - __bfloat162float(ha);
    float rb = b - __bfloat162float(hb);
    __nv_bfloat16 la = __float2bfloat16_rn(ra);
    __nv_bfloat16 lb = __float2bfloat16_rn(rb);
    lo = ((uint32_t)__bfloat16_as_ushort(lb) << 16) | (uint32_t)__bfloat16_as_ushort(la);
    return ((uint32_t)__bfloat16_as_ushort(hb) << 16) | (uint32_t)__bfloat16_as_ushort(ha);
}

__device__ __forceinline__ void split8(const float* v, uint4& hi, uint4& lo) {
    uint32_t l0, l1, l2, l3;
    hi.x = bsplit2(v[0], v[1], l0);
    hi.y = bsplit2(v[2], v[3], l1);
    hi.z = bsplit2(v[4], v[5], l2);
    hi.w = bsplit2(v[6], v[7], l3);
    lo.x = l0; lo.y = l1; lo.z = l2; lo.w = l3;
}

// Register-resident guarded top-17 insert (descending u64 keys, all static idx).
__device__ __forceinline__ void ins17(unsigned long long* a, unsigned long long key) {
    if (key > a[16]) {
        #pragma unroll
        for (int j = 16; j > 0; j--) {
            unsigned long long pj = a[j-1];
            a[j] = (key > pj) ? pj : ((key > a[j]) ? key : a[j]);
        }
        if (key > a[0]) a[0] = key;
    }
}

// ---------------------------------------------------------------------------
// inv_freq: 64 double pow calls only (bit-identical to reference).
// ---------------------------------------------------------------------------
__global__ void invf_kernel() {
    int j = threadIdx.x;
    double e = (double)(2 * j) / 128.0;
    double p = pow(10000.0, e);
    float pf = (float)p;
    g_invf[j] = 1.0f / pf;
}

// ---------------------------------------------------------------------------
// Custom double sincos (Cody-Waite + fdlibm polys); bit-matches libm at f32.
// ---------------------------------------------------------------------------
__device__ __forceinline__ void dsincos_f(float angf, float* cs, float* sn) {
    const double pio2_1  = 1.57079632673412561417e+00;
    const double pio2_1t = 6.07710050650619224932e-11;
    double x = (double)angf;
    double kd = rint(x * 6.36619772367581382433e-01);
    double r = x - kd * pio2_1;
    r = r - kd * pio2_1t;
    double z = r * r;
    double ps = 1.58969099521155010221e-10;
    ps = ps * z + -2.50507602534068634195e-08;
    ps = ps * z +  2.75573137070700676789e-06;
    ps = ps * z + -1.98412698298579493134e-04;
    ps = ps * z +  8.33333333332248946124e-03;
    ps = ps * z + -1.66666666666666324348e-01;
    double s = r + r * z * ps;
    double pc = -1.13596475577881948265e-11;
    pc = pc * z +  2.08757232129817482790e-09;
    pc = pc * z + -2.75573143513906633035e-07;
    pc = pc * z +  2.48015872894767294178e-05;
    pc = pc * z + -1.38888888888741095749e-03;
    pc = pc * z +  4.16666666666666019037e-02;
    double c = 1.0 + z * (-0.5 + z * pc);
    int q = ((int)kd) & 3;
    double sv, cv;
    if (q == 0)      { sv = s;  cv = c;  }
    else if (q == 1) { sv = c;  cv = -s; }
    else if (q == 2) { sv = -s; cv = -c; }
    else             { sv = -c; cv = s;  }
    *sn = (float)sv;
    *cs = (float)cv;
}

__global__ void table_kernel() {
    int s = blockIdx.x;
    int j = threadIdx.x;
    float ang = __fmul_rn((float)s, g_invf[j]);
    float c, sn;
    dsincos_f(ang, &c, &sn);
    g_cos[s * 64 + j] = c;
    g_sin[s * 64 + j] = sn;
}

// ---------------------------------------------------------------------------
// Fused RoPE + split-bf16 planes + krot f32.
// ---------------------------------------------------------------------------
__global__ void rope_split_kernel(const float* __restrict__ q, const float* __restrict__ k,
                                  const int* __restrict__ pos_ids) {
    int idx = blockIdx.x * 256 + threadIdx.x;
    if (idx >= BHN * SS * 8) return;
    int c = idx & 7;
    int s = (idx >> 3) & 2047;
    int bh = idx >> 14;
    int b = bh >> 5;
    int pos = pos_ids[b * SS + s];
    int d0 = c * 8;
    size_t rb = ((size_t)bh * SS + s) * DD;

    float xq[8], yq[8], xk[8], yk[8], cs[8], sn[8];
    *(float4*)&xq[0] = *(const float4*)&q[rb + d0];
    *(float4*)&xq[4] = *(const float4*)&q[rb + d0 + 4];
    *(float4*)&yq[0] = *(const float4*)&q[rb + d0 + 64];
    *(float4*)&yq[4] = *(const float4*)&q[rb + d0 + 68];
    *(float4*)&xk[0] = *(const float4*)&k[rb + d0];
    *(float4*)&xk[4] = *(const float4*)&k[rb + d0 + 4];
    *(float4*)&yk[0] = *(const float4*)&k[rb + d0 + 64];
    *(float4*)&yk[4] = *(const float4*)&k[rb + d0 + 68];
    #pragma unroll
    for (int i = 0; i < 8; i++) {
        cs[i] = g_cos[pos * 64 + d0 + i];
        sn[i] = g_sin[pos * 64 + d0 + i];
    }

    float loq[8], upq[8], lok[8], upk[8];
    #pragma unroll
    for (int i = 0; i < 8; i++) {
        loq[i] = __fsub_rn(__fmul_rn(xq[i], cs[i]), __fmul_rn(yq[i], sn[i]));
        upq[i] = __fadd_rn(__fmul_rn(yq[i], cs[i]), __fmul_rn(xq[i], sn[i]));
        lok[i] = __fsub_rn(__fmul_rn(xk[i], cs[i]), __fmul_rn(yk[i], sn[i]));
        upk[i] = __fadd_rn(__fmul_rn(yk[i], cs[i]), __fmul_rn(xk[i], sn[i]));
    }

    *(float4*)&g_krot[rb + d0]      = *(float4*)&lok[0];
    *(float4*)&g_krot[rb + d0 + 4]  = *(float4*)&lok[4];
    *(float4*)&g_krot[rb + d0 + 64] = *(float4*)&upk[0];
    *(float4*)&g_krot[rb + d0 + 68] = *(float4*)&upk[4];

    size_t rowb = ((size_t)bh * SS + s) * 16;
    int pcl = c ^ (s & 7);
    int pcu = 8 + pcl;
    uint4 hi, lo;
    split8(loq, hi, lo); g_qh[rowb + pcl] = hi; g_ql[rowb + pcl] = lo;
    split8(upq, hi, lo); g_qh[rowb + pcu] = hi; g_ql[rowb + pcu] = lo;
    split8(lok, hi, lo); g_kh[rowb + pcl] = hi; g_kl[rowb + pcl] = lo;
    split8(upk, hi, lo); g_kh[rowb + pcu] = hi; g_kl[rowb + pcu] = lo;
}

// ---------------------------------------------------------------------------
// V split planes.
// ---------------------------------------------------------------------------
__global__ void v_split_kernel(const float* __restrict__ v) {
    int idx = blockIdx.x * 256 + threadIdx.x;
    if (idx >= BHN * SS * 16) return;
    int c = idx & 15;
    int s = (idx >> 4) & 2047;
    int bh = idx >> 15;
    size_t rb = ((size_t)bh * SS + s) * DD;
    float x[8];
    *(float4*)&x[0] = *(const float4*)&v[rb + c * 8];
    *(float4*)&x[4] = *(const float4*)&v[rb + c * 8 + 4];
    uint4 hi, lo;
    split8(x, hi, lo);
    size_t rowb = ((size_t)bh * SS + s) * 16;
    int pc = c ^ (s & 7);
    g_vh[rowb + pc] = hi;
    g_vl[rowb + pc] = lo;
}

// ---------------------------------------------------------------------------
// Flash attention via mma.sync m16n8k16 bf16 (3-pass split), no-rescale softmax.
// Q fragments hoisted to registers; K/V double-buffered via cp.async.
// Smem: 2 stages x 64KB; stage layout: KH 0, KL 16K, VH 32K, VL 48K.
// ---------------------------------------------------------------------------
#define STG 65536
#define SM_TOT 131072

__global__ __launch_bounds__(256, 1)
void attn_mma_kernel(const uint4* __restrict__ pqh, const uint4* __restrict__ pql,
                     const uint4* __restrict__ pkh, const uint4* __restrict__ pkl,
                     const uint4* __restrict__ pvh, const uint4* __restrict__ pvl,
                     float* __restrict__ out) {
    extern __shared__ char smc[];
    const int tid = threadIdx.x;
    const int w = tid >> 5, l = tid & 31;
    const int qb = 15 - (int)blockIdx.x;     // heavy blocks first
    const int bh = blockIdx.y;
    const uint32_t sb = smem_u32(smc);

    const int rowmin = qb * 128 + w * 16;
    const int row0 = rowmin + (l >> 2);
    const int aR = ((l >> 3) & 1) * 8 + (l & 7);
    const int aK = ((l >> 4) & 1) * 8;
    const int bR = ((l >> 4) & 1) * 8 + (l & 7);
    const int bK = ((l >> 3) & 1) * 8;
    const int vR = ((l >> 3) & 1) * 8 + (l & 7);
    const int vD = ((l >> 4) & 1) * 8;
    const float sc = 0.088388347648318447f * 1.4426950408889634f;
    const int nt = 2 * (qb + 1);

    // ---- Stage Q into smem (cp.async), then hoist fragments to registers ----
    {
        size_t qsrc = ((size_t)bh * SS + (size_t)qb * 128) * 16;
        #pragma unroll
        for (int j = 0; j < 8; j++) {
            int i = tid + j * 256;     // 0..2047
            CP_ASYNC16(sb + i * 16, pqh + qsrc + i);
            CP_ASYNC16(sb + 32768 + i * 16, pql + qsrc + i);
        }
        CP_COMMIT();
        CP_WAIT0();
    }
    __syncthreads();

    uint32_t qh[8][4], ql[8][4];
    #pragma unroll
    for (int ks = 0; ks < 8; ks++) {
        uint32_t qaddr = sb + soff(w * 16 + aR, ks * 16 + aK);
        LDSM4(qh[ks], qaddr);
        LDSM4(ql[ks], qaddr + 32768);
    }
    __syncthreads();   // Q regs captured; smem may be overwritten by K/V

    // ---- Prefetch tile 0 into stage 0 ----
    {
        size_t src = (size_t)bh * SS * 16;
        #pragma unroll
        for (int j = 0; j < 4; j++) {
            int i = tid + j * 256;     // 0..1023
            CP_ASYNC16(sb + i * 16,         pkh + src + i);
            CP_ASYNC16(sb + 16384 + i * 16, pkl + src + i);
            CP_ASYNC16(sb + 32768 + i * 16, pvh + src + i);
            CP_ASYNC16(sb + 49152 + i * 16, pvl + src + i);
        }
        CP_COMMIT();
    }

    float o_[16][4];
    #pragma unroll
    for (int i = 0; i < 16; i++)
        #pragma unroll
        for (int j = 0; j < 4; j++) o_[i][j] = 0.0f;
    float lsum0 = 0.0f, lsum1 = 0.0f;

    for (int t = 0; t < nt; t++) {
        // Prefetch next tile into the other stage
        if (t + 1 < nt) {
            uint32_t st = sb + ((t + 1) & 1) * STG;
            size_t src = ((size_t)bh * SS + (size_t)(t + 1) * 64) * 16;
            #pragma unroll
            for (int j = 0; j < 4; j++) {
                int i = tid + j * 256;
                CP_ASYNC16(st + i * 16,         pkh + src + i);
                CP_ASYNC16(st + 16384 + i * 16, pkl + src + i);
                CP_ASYNC16(st + 32768 + i * 16, pvh + src + i);
                CP_ASYNC16(st + 49152 + i * 16, pvl + src + i);
            }
            CP_COMMIT();
            CP_WAIT1();   // tile t complete (only t+1 group may remain)
        } else {
            CP_WAIT0();
        }
        __syncthreads();

        const uint32_t st = sb + (t & 1) * STG;
        const bool active = (64 * t <= rowmin + 15);

        if (active) {
            // ---- S = Qhi*Khi + Qlo*Khi + Qhi*Klo ----
            float s_[8][4];
            #pragma unroll
            for (int i = 0; i < 8; i++)
                #pragma unroll
                for (int j = 0; j < 4; j++) s_[i][j] = 0.0f;

            #pragma unroll
            for (int ks = 0; ks < 8; ks++) {
                #pragma unroll
                for (int n0 = 0; n0 < 4; n0++) {
                    uint32_t kh_[4], kl_[4];
                    uint32_t baddr = st + soff(n0 * 16 + bR, ks * 16 + bK);
                    LDSM4(kh_, baddr);
                    LDSM4(kl_, baddr + 16384);
                    MMA16816(s_[2*n0],   qh[ks][0],qh[ks][1],qh[ks][2],qh[ks][3], kh_[0], kh_[1]);
                    MMA16816(s_[2*n0],   ql[ks][0],ql[ks][1],ql[ks][2],ql[ks][3], kh_[0], kh_[1]);
                    MMA16816(s_[2*n0],   qh[ks][0],qh[ks][1],qh[ks][2],qh[ks][3], kl_[0], kl_[1]);
                    MMA16816(s_[2*n0+1], qh[ks][0],qh[ks][1],qh[ks][2],qh[ks][3], kh_[2], kh_[3]);
                    MMA16816(s_[2*n0+1], ql[ks][0],ql[ks][1],ql[ks][2],ql[ks][3], kh_[2], kh_[3]);
                    MMA16816(s_[2*n0+1], qh[ks][0],qh[ks][1],qh[ks][2],qh[ks][3], kl_[2], kl_[3]);
                }
            }

            // ---- softmax (no rescale), build P fragments in regs ----
            const bool needmask = (64 * t + 63 > rowmin);
            uint32_t phi[8][2], plo[8][2];
            const int colb = 64 * t + 2 * (l & 3);
            #pragma unroll
            for (int n2 = 0; n2 < 8; n2++) {
                float p0 = ex2f(s_[n2][0] * sc);
                float p1 = ex2f(s_[n2][1] * sc);
                float p2 = ex2f(s_[n2][2] * sc);
                float p3 = ex2f(s_[n2][3] * sc);
                if (needmask) {
                    int c0 = colb + 8 * n2;
                    if (c0     > row0)     p0 = 0.0f;
                    if (c0 + 1 > row0)     p1 = 0.0f;
                    if (c0     > row0 + 8) p2 = 0.0f;
                    if (c0 + 1 > row0 + 8) p3 = 0.0f;
                }
                lsum0 += p0 + p1;
                lsum1 += p2 + p3;
                uint32_t t0, t1;
                phi[n2][0] = bsplit2(p0, p1, t0); plo[n2][0] = t0;
                phi[n2][1] = bsplit2(p2, p3, t1); plo[n2][1] = t1;
            }

            // ---- O += Phi*Vhi + Plo*Vhi + Phi*Vlo ----
            #pragma unroll
            for (int ks = 0; ks < 4; ks++) {
                uint32_t A0 = phi[2*ks][0], A1 = phi[2*ks][1];
                uint32_t A2 = phi[2*ks+1][0], A3 = phi[2*ks+1][1];
                uint32_t L0 = plo[2*ks][0], L1 = plo[2*ks][1];
                uint32_t L2 = plo[2*ks+1][0], L3 = plo[2*ks+1][1];
                #pragma unroll
                for (int d0 = 0; d0 < 8; d0++) {
                    uint32_t vh_[4], vl_[4];
                    uint32_t vaddr = st + 32768 + soff(ks * 16 + vR, d0 * 16 + vD);
                    LDSM4T(vh_, vaddr);
                    LDSM4T(vl_, vaddr + 16384);
                    MMA16816(o_[2*d0],   A0,A1,A2,A3, vh_[0], vh_[1]);
                    MMA16816(o_[2*d0],   L0,L1,L2,L3, vh_[0], vh_[1]);
                    MMA16816(o_[2*d0],   A0,A1,A2,A3, vl_[0], vl_[1]);
                    MMA16816(o_[2*d0+1], A0,A1,A2,A3, vh_[2], vh_[3]);
                    MMA16816(o_[2*d0+1], L0,L1,L2,L3, vh_[2], vh_[3]);
                    MMA16816(o_[2*d0+1], A0,A1,A2,A3, vl_[2], vl_[3]);
                }
            }
        }
        __syncthreads();   // all warps done with stage (t&1) before it is re-filled
    }

    // ---- epilogue: reduce l over quad, normalize, store ----
    lsum0 += __shfl_xor_sync(0xffffffffu, lsum0, 1);
    lsum0 += __shfl_xor_sync(0xffffffffu, lsum0, 2);
    lsum1 += __shfl_xor_sync(0xffffffffu, lsum1, 1);
    lsum1 += __shfl_xor_sync(0xffffffffu, lsum1, 2);
    float inv0 = 1.0f / lsum0;
    float inv1 = 1.0f / lsum1;
    size_t rbase = OFF_ATTN + ((size_t)bh * SS + row0) * DD;
    #pragma unroll
    for (int n2 = 0; n2 < 16; n2++) {
        int d = n2 * 8 + 2 * (l & 3);
        float2 a = {o_[n2][0] * inv0, o_[n2][1] * inv0};
        float2 b = {o_[n2][2] * inv1, o_[n2][3] * inv1};
        *(float2*)&out[rbase + d] = a;
        *(float2*)&out[rbase + 8 * DD + d] = b;
    }
}

// ---------------------------------------------------------------------------
// K top-k pipeline. Keys = (abs_bits << 32) | (4095 - s): abs desc, idx asc.
// ---------------------------------------------------------------------------
__global__ void kq_partial(const float* __restrict__ kr) {
    int bh = blockIdx.x, ch = blockIdx.y, d = threadIdx.x;
    unsigned long long a[17];
    #pragma unroll
    for (int i = 0; i < 17; i++) a[i] = 0ull;

    int s0 = ch * 128;
    const float* p = kr + ((size_t)bh * SS + s0) * DD + d;
    int ibeg = (ch == 0) ? 4 : 0;
    for (int i = ibeg; i < 128; i++) {
        float v = p[(size_t)i * DD];
        unsigned ab = __float_as_uint(fabsf(v));
        unsigned long long key = ((unsigned long long)ab << 32) | (unsigned)(4095 - (s0 + i));
        ins17(a, key);
    }
    unsigned long long* dst = g_pk + (((size_t)bh * DD + d) * 16 + ch) * 17;
    #pragma unroll
    for (int i = 0; i < 17; i++) dst[i] = a[i];
}

__global__ void kq_merge(const float* __restrict__ kr, float* __restrict__ out) {
    int bh = blockIdx.x, d = threadIdx.x;
    unsigned long long a[17];
    #pragma unroll
    for (int i = 0; i < 17; i++) a[i] = 0ull;

    const unsigned long long* pk = g_pk + ((size_t)bh * DD + d) * 16 * 17;
    for (int t = 0; t < 16 * 17; t++) ins17(a, pk[t]);

    float absmax = __uint_as_float((unsigned)(a[16] >> 32));
    float scale = fmaxf(absmax, 1e-8f) / 127.0f;
    out[OFF_KSCALE + (size_t)bh * DD + d] = scale;

    size_t sp = ((size_t)bh * DD + d) * 16;
    int idxs[16];
    #pragma unroll
    for (int i = 0; i < 16; i++) {
        int s = 4095 - (int)(unsigned)(a[i] & 0xFFFFFFFFull);
        idxs[i] = s;
        out[OFF_KSPI + sp + i] = (float)s;
        out[OFF_KSPV + sp + i] = kr[((size_t)bh * SS + s) * DD + d];
    }

    unsigned m[64];
    for (int w = 0; w < 64; w++) m[w] = 0u;
    #pragma unroll
    for (int i = 0; i < 16; i++) m[idxs[i] >> 5] |= (1u << (idxs[i] & 31));
    for (int w = 0; w < 64; w++)
        g_mask[((size_t)bh * 64 + w) * DD + d] = m[w];
}

__global__ __launch_bounds__(256)
void kq_write(const float* __restrict__ kr, float* __restrict__ out) {
    __shared__ unsigned smask[512];
    __shared__ float sscale[128];
    int bh = blockIdx.x, scn = blockIdx.y;
    int tid = threadIdx.x;

    for (int i = tid; i < 512; i += 256) {
        int w4 = i >> 7, d = i & 127;
        smask[i] = g_mask[((size_t)bh * 64 + scn * 4 + w4) * DD + d];
    }
    if (tid < 128) sscale[tid] = out[OFF_KSCALE + (size_t)bh * DD + tid];
    __syncthreads();

    for (int u = tid; u < 4096; u += 256) {
        int r = u >> 5, d4 = u & 31;
        int s = scn * 128 + r;
        size_t off = ((size_t)bh * SS + s) * DD + d4 * 4;
        float4 v = *(const float4*)(kr + off);
        int w4 = r >> 5;
        int bit = s & 31;
        float vv[4] = {v.x, v.y, v.z, v.w};
        float q[4];
        #pragma unroll
        for (int j = 0; j < 4; j++) {
            int dd = d4 * 4 + j;
            bool z = (s < 4) || ((smask[w4 * 128 + dd] >> bit) & 1u);
            if (z) {
                q[j] = 0.0f;
            } else {
                float r2 = rintf(vv[j] / sscale[dd]);
                q[j] = fminf(fmaxf(r2, -127.0f), 127.0f);
            }
        }
        float4 qo = {q[0], q[1], q[2], q[3]};
        *(float4*)&out[OFF_KQ + off] = qo;
    }
}

// ---------------------------------------------------------------------------
// V side: warp per token. top-5 of |v| over D=128 (abs desc, idx asc ties).
// ---------------------------------------------------------------------------
__global__ void vquant_kernel(const float* __restrict__ v, float* __restrict__ out) {
    int gwarp = (int)((blockIdx.x * (size_t)blockDim.x + threadIdx.x) >> 5);
    int lane = threadIdx.x & 31;
    if (gwarp >= BHN * SS) return;
    int s = gwarp & (SS - 1);

    const float* row = v + (size_t)gwarp * DD;
    float4 x = *(const float4*)(row + lane * 4);
    float vals[4] = {x.x, x.y, x.z, x.w};

    int tidx[4] = {0, 1, 2, 3};
    float tval[4] = {0.0f, 0.0f, 0.0f, 0.0f};
    float absmax = 0.0f;
    bool sink = (s < 4);

    if (!sink) {
        unsigned used = 0u;
        unsigned long long keys[4];
        #pragma unroll
        for (int i = 0; i < 4; i++) {
            unsigned ab = __float_as_uint(fabsf(vals[i]));
            keys[i] = ((unsigned long long)ab << 32) | (unsigned)(127 - (lane * 4 + i));
        }
        for (int rnd = 0; rnd < 5; rnd++) {
            unsigned long long best = 0ull;
            #pragma unroll
            for (int i = 0; i < 4; i++)
                if (!((used >> i) & 1u) && keys[i] > best) best = keys[i];
            #pragma unroll
            for (int off = 16; off >= 1; off >>= 1) {
                unsigned long long o2 = __shfl_xor_sync(0xffffffffu, best, off);
                if (o2 > best) best = o2;
            }
            int gidx = 127 - (int)(unsigned)(best & 0xffffffffull);
            float ab = __uint_as_float((unsigned)(best >> 32));
            int owner = gidx >> 2, slot = gidx & 3;
            if (lane == owner) used |= (1u << slot);
            if (rnd < 4) {
                float cand = (slot == 0) ? vals[0] : (slot == 1) ? vals[1]
                           : (slot == 2) ? vals[2] : vals[3];
                float sv = __shfl_sync(0xffffffffu, cand, owner);
                tidx[rnd] = gidx;
                tval[rnd] = sv;
            } else {
                absmax = ab;
            }
        }
    }

    float scale = fmaxf(absmax, 1e-8f) / 127.0f;

    float q[4];
    #pragma unroll
    for (int i = 0; i < 4; i++) {
        int gi = lane * 4 + i;
        bool zero = sink | (gi == tidx[0]) | (gi == tidx[1]) | (gi == tidx[2]) | (gi == tidx[3]);
        if (zero) {
            q[i] = 0.0f;
        } else {
            float r = rintf(vals[i] / scale);
            q[i] = fminf(fmaxf(r, -127.0f), 127.0f);
        }
    }
    float4 qo = {q[0], q[1], q[2], q[3]};
    *(float4*)&out[OFF_VQ + (size_t)gwarp * DD + lane * 4] = qo;

    if (lane == 0) {
        out[OFF_VSCALE + gwarp] = scale;
        #pragma unroll
        for (int t = 0; t < 4; t++) {
            out[OFF_VSPV + (size_t)gwarp * 4 + t] = tval[t];
            out[OFF_VSPI + (size_t)gwarp * 4 + t] = (float)tidx[t];
        }
    }
}

// ---------------------------------------------------------------------------
extern "C" void kernel_launch(void* const* d_in, const int* in_sizes, int n_in,
                              void* d_out, int out_size) {
    const float* q = (const float*)d_in[0];
    const float* k = (const float*)d_in[1];
    const float* v = (const float*)d_in[2];
    const int* pos = (const int*)d_in[3];
    float* out = (float*)d_out;

    float* krot; cudaGetSymbolAddress((void**)&krot, g_krot);
    uint4 *pqh, *pql, *pkh, *pkl, *pvh, *pvl;
    cudaGetSymbolAddress((void**)&pqh, g_qh);
    cudaGetSymbolAddress((void**)&pql, g_ql);
    cudaGetSymbolAddress((void**)&pkh, g_kh);
    cudaGetSymbolAddress((void**)&pkl, g_kl);
    cudaGetSymbolAddress((void**)&pvh, g_vh);
    cudaGetSymbolAddress((void**)&pvl, g_vl);

    // 1. inv_freq + cos/sin table
    invf_kernel<<<1, 64>>>();
    table_kernel<<<SS, 64>>>();

    // 2. Fused RoPE + bf16 split planes (Q, K) + krot f32
    rope_split_kernel<<<(BHN * SS * 8 + 255) / 256, 256>>>(q, k, pos);

    // 3. V split planes
    v_split_kernel<<<(BHN * SS * 16 + 255) / 256, 256>>>(v);

    // 4. Attention (mma.sync bf16, 3-pass split, Q-in-regs, cp.async pipeline)
    {
        cudaFuncSetAttribute(attn_mma_kernel, cudaFuncAttributeMaxDynamicSharedMemorySize, SM_TOT);
        dim3 grid(16, BHN);
        attn_mma_kernel<<<grid, 256, SM_TOT>>>(pqh, pql, pkh, pkl, pvh, pvl, out);
    }

    // 5. K quant pipeline: partial top-17 -> merge -> quantize
    {
        dim3 gp(BHN, 16);
        kq_partial<<<gp, 128>>>(krot);
        kq_merge<<<BHN, 128>>>(krot, out);
        dim3 gw(BHN, 16);
        kq_write<<<gw, 256>>>(krot, out);
    }

    // 6. V quant + outliers
    {
        int warps = BHN * SS;
        int threads = 256;
        int blocks = (warps * 32 + threads - 1) / threads;
        vquant_kernel<<<blocks, threads>>>(v, out);
    }
}

// round 13
// speedup vs baseline: 8.4140x; 1.2149x over previous
#include <cuda_runtime.h>
#include <cuda_bf16.h>
#include <cuda_fp16.h>
#include <math.h>
#include <stdint.h>

// Problem dims
#define BB 2
#define HH 32
#define SS 2048
#define DD 128
#define BHN (BB*HH)

// Output layout (floats), concatenated in reference return order
#define OFF_ATTN   ((size_t)0)
#define OFF_KQ     ((size_t)16777216)
#define OFF_KSCALE ((size_t)33554432)
#define OFF_VQ     ((size_t)33562624)
#define OFF_VSCALE ((size_t)50339840)
#define OFF_KSPV   ((size_t)50470912)
#define OFF_KSPI   ((size_t)50601984)
#define OFF_VSPV   ((size_t)50733056)
#define OFF_VSPI   ((size_t)51257344)

// Scratch (device globals: no allocation allowed)
__device__ float g_krot[BB*HH*SS*DD];
__device__ float g_invf[64];
__device__ float g_cos[SS*64];
__device__ float g_sin[SS*64];
// fp16 planes, pre-swizzled rows of 256B (16 x 16B chunks, chunk ^= row&7)
__device__ uint4 g_qh[BHN*SS*16];   // fp16(q_rot) hi
__device__ uint4 g_ql[BHN*SS*16];   // fp16 residual of q_rot
__device__ uint4 g_kb[BHN*SS*16];   // fp16(k_rot), unsplit
__device__ uint4 g_vb[BHN*SS*16];   // fp16(v), unsplit
// K top-k pipeline scratch
__device__ unsigned long long g_pk[BHN*DD*16*17];   // partial top-17 keys
__device__ unsigned g_mask[BHN*64*DD];              // outlier bitmap [bh][w][d]

// ===========================================================================
// helpers
// ===========================================================================
__device__ __forceinline__ uint32_t smem_u32(const void* p) {
    uint32_t a;
    asm("{ .reg .u64 t; cvta.to.shared.u64 t, %1; cvt.u32.u64 %0, t; }"
        : "=r"(a) : "l"(p));
    return a;
}

// swizzled byte offset within a [rows][128 fp16] tile, 256B row pitch
__device__ __forceinline__ int soff(int r, int d) {
    return r * 256 + ((((d >> 3) ^ (r & 7)) & 15) << 4) + ((d & 7) << 1);
}

#define LDSM4(r, a) \
    asm volatile("ldmatrix.sync.aligned.m8n8.x4.shared.b16 {%0,%1,%2,%3}, [%4];" \
        : "=r"((r)[0]), "=r"((r)[1]), "=r"((r)[2]), "=r"((r)[3]) : "r"(a))
#define LDSM4T(r, a) \
    asm volatile("ldmatrix.sync.aligned.m8n8.x4.trans.shared.b16 {%0,%1,%2,%3}, [%4];" \
        : "=r"((r)[0]), "=r"((r)[1]), "=r"((r)[2]), "=r"((r)[3]) : "r"(a))

#define MMAH16816(c, a0,a1,a2,a3, b0,b1) \
    asm volatile("mma.sync.aligned.m16n8k16.row.col.f32.f16.f16.f32 " \
        "{%0,%1,%2,%3}, {%4,%5,%6,%7}, {%8,%9}, {%0,%1,%2,%3};" \
        : "+f"((c)[0]), "+f"((c)[1]), "+f"((c)[2]), "+f"((c)[3]) \
        : "r"(a0), "r"(a1), "r"(a2), "r"(a3), "r"(b0), "r"(b1))

#define CP_ASYNC16(dst, src) \
    asm volatile("cp.async.cg.shared.global [%0], [%1], 16;" \
        :: "r"(dst), "l"(src) : "memory")
#define CP_COMMIT() asm volatile("cp.async.commit_group;" ::: "memory")
#define CP_WAIT0()  asm volatile("cp.async.wait_group 0;" ::: "memory")
#define CP_WAIT1()  asm volatile("cp.async.wait_group 1;" ::: "memory")

__device__ __forceinline__ float ex2f(float x) {
    float y;
    asm("ex2.approx.f32 %0, %1;" : "=f"(y) : "f"(x));
    return y;
}

// pack two floats to fp16x2 (rn)
__device__ __forceinline__ uint32_t pk2h(float a, float b) {
    __half ha = __float2half_rn(a);
    __half hb = __float2half_rn(b);
    return ((uint32_t)__half_as_ushort(hb) << 16) | (uint32_t)__half_as_ushort(ha);
}

__device__ __forceinline__ uint4 pack8h(const float* v) {
    uint4 r;
    r.x = pk2h(v[0], v[1]);
    r.y = pk2h(v[2], v[3]);
    r.z = pk2h(v[4], v[5]);
    r.w = pk2h(v[6], v[7]);
    return r;
}

// fp16 split: hi = fp16(a,b), lo = fp16 residuals
__device__ __forceinline__ uint32_t hsplit2(float a, float b, uint32_t& lo) {
    __half ha = __float2half_rn(a);
    __half hb = __float2half_rn(b);
    float ra = a - __half2float(ha);
    float rb = b - __half2float(hb);
    __half la = __float2half_rn(ra);
    __half lb = __float2half_rn(rb);
    lo = ((uint32_t)__half_as_ushort(lb) << 16) | (uint32_t)__half_as_ushort(la);
    return ((uint32_t)__half_as_ushort(hb) << 16) | (uint32_t)__half_as_ushort(ha);
}

__device__ __forceinline__ void split8h(const float* v, uint4& hi, uint4& lo) {
    uint32_t l0, l1, l2, l3;
    hi.x = hsplit2(v[0], v[1], l0);
    hi.y = hsplit2(v[2], v[3], l1);
    hi.z = hsplit2(v[4], v[5], l2);
    hi.w = hsplit2(v[6], v[7], l3);
    lo.x = l0; lo.y = l1; lo.z = l2; lo.w = l3;
}

// Register-resident guarded top-17 insert (descending u64 keys, all static idx).
__device__ __forceinline__ void ins17(unsigned long long* a, unsigned long long key) {
    if (key > a[16]) {
        #pragma unroll
        for (int j = 16; j > 0; j--) {
            unsigned long long pj = a[j-1];
            a[j] = (key > pj) ? pj : ((key > a[j]) ? key : a[j]);
        }
        if (key > a[0]) a[0] = key;
    }
}

// ---------------------------------------------------------------------------
// inv_freq: 64 double pow calls only (bit-identical to reference).
// ---------------------------------------------------------------------------
__global__ void invf_kernel() {
    int j = threadIdx.x;
    double e = (double)(2 * j) / 128.0;
    double p = pow(10000.0, e);
    float pf = (float)p;
    g_invf[j] = 1.0f / pf;
}

// ---------------------------------------------------------------------------
// Custom double sincos (Cody-Waite + fdlibm polys); bit-matches libm at f32.
// ---------------------------------------------------------------------------
__device__ __forceinline__ void dsincos_f(float angf, float* cs, float* sn) {
    const double pio2_1  = 1.57079632673412561417e+00;
    const double pio2_1t = 6.07710050650619224932e-11;
    double x = (double)angf;
    double kd = rint(x * 6.36619772367581382433e-01);
    double r = x - kd * pio2_1;
    r = r - kd * pio2_1t;
    double z = r * r;
    double ps = 1.58969099521155010221e-10;
    ps = ps * z + -2.50507602534068634195e-08;
    ps = ps * z +  2.75573137070700676789e-06;
    ps = ps * z + -1.98412698298579493134e-04;
    ps = ps * z +  8.33333333332248946124e-03;
    ps = ps * z + -1.66666666666666324348e-01;
    double s = r + r * z * ps;
    double pc = -1.13596475577881948265e-11;
    pc = pc * z +  2.08757232129817482790e-09;
    pc = pc * z + -2.75573143513906633035e-07;
    pc = pc * z +  2.48015872894767294178e-05;
    pc = pc * z + -1.38888888888741095749e-03;
    pc = pc * z +  4.16666666666666019037e-02;
    double c = 1.0 + z * (-0.5 + z * pc);
    int q = ((int)kd) & 3;
    double sv, cv;
    if (q == 0)      { sv = s;  cv = c;  }
    else if (q == 1) { sv = c;  cv = -s; }
    else if (q == 2) { sv = -s; cv = -c; }
    else             { sv = -c; cv = s;  }
    *sn = (float)sv;
    *cs = (float)cv;
}

__global__ void table_kernel() {
    int s = blockIdx.x;
    int j = threadIdx.x;
    float ang = __fmul_rn((float)s, g_invf[j]);
    float c, sn;
    dsincos_f(ang, &c, &sn);
    g_cos[s * 64 + j] = c;
    g_sin[s * 64 + j] = sn;
}

// ---------------------------------------------------------------------------
// Fused RoPE + fp16 planes (Q split hi/lo, K unsplit) + krot f32.
// ---------------------------------------------------------------------------
__global__ void rope_split_kernel(const float* __restrict__ q, const float* __restrict__ k,
                                  const int* __restrict__ pos_ids) {
    int idx = blockIdx.x * 256 + threadIdx.x;
    if (idx >= BHN * SS * 8) return;
    int c = idx & 7;
    int s = (idx >> 3) & 2047;
    int bh = idx >> 14;
    int b = bh >> 5;
    int pos = pos_ids[b * SS + s];
    int d0 = c * 8;
    size_t rb = ((size_t)bh * SS + s) * DD;

    float xq[8], yq[8], xk[8], yk[8], cs[8], sn[8];
    *(float4*)&xq[0] = *(const float4*)&q[rb + d0];
    *(float4*)&xq[4] = *(const float4*)&q[rb + d0 + 4];
    *(float4*)&yq[0] = *(const float4*)&q[rb + d0 + 64];
    *(float4*)&yq[4] = *(const float4*)&q[rb + d0 + 68];
    *(float4*)&xk[0] = *(const float4*)&k[rb + d0];
    *(float4*)&xk[4] = *(const float4*)&k[rb + d0 + 4];
    *(float4*)&yk[0] = *(const float4*)&k[rb + d0 + 64];
    *(float4*)&yk[4] = *(const float4*)&k[rb + d0 + 68];
    #pragma unroll
    for (int i = 0; i < 8; i++) {
        cs[i] = g_cos[pos * 64 + d0 + i];
        sn[i] = g_sin[pos * 64 + d0 + i];
    }

    float loq[8], upq[8], lok[8], upk[8];
    #pragma unroll
    for (int i = 0; i < 8; i++) {
        loq[i] = __fsub_rn(__fmul_rn(xq[i], cs[i]), __fmul_rn(yq[i], sn[i]));
        upq[i] = __fadd_rn(__fmul_rn(yq[i], cs[i]), __fmul_rn(xq[i], sn[i]));
        lok[i] = __fsub_rn(__fmul_rn(xk[i], cs[i]), __fmul_rn(yk[i], sn[i]));
        upk[i] = __fadd_rn(__fmul_rn(yk[i], cs[i]), __fmul_rn(xk[i], sn[i]));
    }

    *(float4*)&g_krot[rb + d0]      = *(float4*)&lok[0];
    *(float4*)&g_krot[rb + d0 + 4]  = *(float4*)&lok[4];
    *(float4*)&g_krot[rb + d0 + 64] = *(float4*)&upk[0];
    *(float4*)&g_krot[rb + d0 + 68] = *(float4*)&upk[4];

    size_t rowb = ((size_t)bh * SS + s) * 16;
    int pcl = c ^ (s & 7);
    int pcu = 8 + pcl;
    uint4 hi, lo;
    split8h(loq, hi, lo); g_qh[rowb + pcl] = hi; g_ql[rowb + pcl] = lo;
    split8h(upq, hi, lo); g_qh[rowb + pcu] = hi; g_ql[rowb + pcu] = lo;
    g_kb[rowb + pcl] = pack8h(lok);
    g_kb[rowb + pcu] = pack8h(upk);
}

// ---------------------------------------------------------------------------
// V fp16 plane (unsplit).
// ---------------------------------------------------------------------------
__global__ void v_split_kernel(const float* __restrict__ v) {
    int idx = blockIdx.x * 256 + threadIdx.x;
    if (idx >= BHN * SS * 16) return;
    int c = idx & 15;
    int s = (idx >> 4) & 2047;
    int bh = idx >> 15;
    size_t rb = ((size_t)bh * SS + s) * DD;
    float x[8];
    *(float4*)&x[0] = *(const float4*)&v[rb + c * 8];
    *(float4*)&x[4] = *(const float4*)&v[rb + c * 8 + 4];
    size_t rowb = ((size_t)bh * SS + s) * 16;
    int pc = c ^ (s & 7);
    g_vb[rowb + pc] = pack8h(x);
}

// ---------------------------------------------------------------------------
// Flash attention, mma.sync m16n8k16 fp16, 2x2-pass split (Q,P split; K,V not).
// No-rescale softmax; Q fragments in registers; K/V double-buffered cp.async.
// Smem: 2 stages x 32KB (K 16K, V 16K); Q hi/lo staged in the 64KB first.
// ---------------------------------------------------------------------------
#define STG 32768
#define SM_TOT 65536

__global__ __launch_bounds__(256, 1)
void attn_mma_kernel(const uint4* __restrict__ pqh, const uint4* __restrict__ pql,
                     const uint4* __restrict__ pkb, const uint4* __restrict__ pvb,
                     float* __restrict__ out) {
    extern __shared__ char smc[];
    const int tid = threadIdx.x;
    const int w = tid >> 5, l = tid & 31;
    const int qb = 15 - (int)blockIdx.x;     // heavy blocks first
    const int bh = blockIdx.y;
    const uint32_t sb = smem_u32(smc);

    const int rowmin = qb * 128 + w * 16;
    const int row0 = rowmin + (l >> 2);
    const int aR = ((l >> 3) & 1) * 8 + (l & 7);
    const int aK = ((l >> 4) & 1) * 8;
    const int bR = ((l >> 4) & 1) * 8 + (l & 7);
    const int bK = ((l >> 3) & 1) * 8;
    const int vR = ((l >> 3) & 1) * 8 + (l & 7);
    const int vD = ((l >> 4) & 1) * 8;
    const float sc = 0.088388347648318447f * 1.4426950408889634f;
    const int nt = 2 * (qb + 1);

    // ---- Stage Q hi/lo into smem (cp.async), hoist fragments to registers ----
    {
        size_t qsrc = ((size_t)bh * SS + (size_t)qb * 128) * 16;
        #pragma unroll
        for (int j = 0; j < 8; j++) {
            int i = tid + j * 256;     // 0..2047
            CP_ASYNC16(sb + i * 16, pqh + qsrc + i);
            CP_ASYNC16(sb + 32768 + i * 16, pql + qsrc + i);
        }
        CP_COMMIT();
        CP_WAIT0();
    }
    __syncthreads();

    uint32_t qh[8][4], ql[8][4];
    #pragma unroll
    for (int ks = 0; ks < 8; ks++) {
        uint32_t qaddr = sb + soff(w * 16 + aR, ks * 16 + aK);
        LDSM4(qh[ks], qaddr);
        LDSM4(ql[ks], qaddr + 32768);
    }
    __syncthreads();   // Q regs captured; smem recycled for K/V stages

    // ---- Prefetch tile 0 into stage 0 ----
    {
        size_t src = (size_t)bh * SS * 16;
        #pragma unroll
        for (int j = 0; j < 4; j++) {
            int i = tid + j * 256;     // 0..1023
            CP_ASYNC16(sb + i * 16,         pkb + src + i);
            CP_ASYNC16(sb + 16384 + i * 16, pvb + src + i);
        }
        CP_COMMIT();
    }

    float o_[16][4];
    #pragma unroll
    for (int i = 0; i < 16; i++)
        #pragma unroll
        for (int j = 0; j < 4; j++) o_[i][j] = 0.0f;
    float lsum0 = 0.0f, lsum1 = 0.0f;

    for (int t = 0; t < nt; t++) {
        if (t + 1 < nt) {
            uint32_t st = sb + ((t + 1) & 1) * STG;
            size_t src = ((size_t)bh * SS + (size_t)(t + 1) * 64) * 16;
            #pragma unroll
            for (int j = 0; j < 4; j++) {
                int i = tid + j * 256;
                CP_ASYNC16(st + i * 16,         pkb + src + i);
                CP_ASYNC16(st + 16384 + i * 16, pvb + src + i);
            }
            CP_COMMIT();
            CP_WAIT1();
        } else {
            CP_WAIT0();
        }
        __syncthreads();

        const uint32_t st = sb + (t & 1) * STG;
        const bool active = (64 * t <= rowmin + 15);

        if (active) {
            // ---- S = Qhi*K + Qlo*K ----
            float s_[8][4];
            #pragma unroll
            for (int i = 0; i < 8; i++)
                #pragma unroll
                for (int j = 0; j < 4; j++) s_[i][j] = 0.0f;

            #pragma unroll
            for (int ks = 0; ks < 8; ks++) {
                #pragma unroll
                for (int n0 = 0; n0 < 4; n0++) {
                    uint32_t kh_[4];
                    LDSM4(kh_, st + soff(n0 * 16 + bR, ks * 16 + bK));
                    MMAH16816(s_[2*n0],   qh[ks][0],qh[ks][1],qh[ks][2],qh[ks][3], kh_[0], kh_[1]);
                    MMAH16816(s_[2*n0],   ql[ks][0],ql[ks][1],ql[ks][2],ql[ks][3], kh_[0], kh_[1]);
                    MMAH16816(s_[2*n0+1], qh[ks][0],qh[ks][1],qh[ks][2],qh[ks][3], kh_[2], kh_[3]);
                    MMAH16816(s_[2*n0+1], ql[ks][0],ql[ks][1],ql[ks][2],ql[ks][3], kh_[2], kh_[3]);
                }
            }

            // ---- softmax (no rescale), build split-fp16 P fragments in regs ----
            const bool needmask = (64 * t + 63 > rowmin);
            uint32_t phi[8][2], plo[8][2];
            const int colb = 64 * t + 2 * (l & 3);
            #pragma unroll
            for (int n2 = 0; n2 < 8; n2++) {
                float p0 = ex2f(s_[n2][0] * sc);
                float p1 = ex2f(s_[n2][1] * sc);
                float p2 = ex2f(s_[n2][2] * sc);
                float p3 = ex2f(s_[n2][3] * sc);
                if (needmask) {
                    int c0 = colb + 8 * n2;
                    if (c0     > row0)     p0 = 0.0f;
                    if (c0 + 1 > row0)     p1 = 0.0f;
                    if (c0     > row0 + 8) p2 = 0.0f;
                    if (c0 + 1 > row0 + 8) p3 = 0.0f;
                }
                lsum0 += p0 + p1;
                lsum1 += p2 + p3;
                uint32_t t0, t1;
                phi[n2][0] = hsplit2(p0, p1, t0); plo[n2][0] = t0;
                phi[n2][1] = hsplit2(p2, p3, t1); plo[n2][1] = t1;
            }

            // ---- O += Phi*V + Plo*V ----
            #pragma unroll
            for (int ks = 0; ks < 4; ks++) {
                uint32_t A0 = phi[2*ks][0], A1 = phi[2*ks][1];
                uint32_t A2 = phi[2*ks+1][0], A3 = phi[2*ks+1][1];
                uint32_t L0 = plo[2*ks][0], L1 = plo[2*ks][1];
                uint32_t L2 = plo[2*ks+1][0], L3 = plo[2*ks+1][1];
                #pragma unroll
                for (int d0 = 0; d0 < 8; d0++) {
                    uint32_t vh_[4];
                    LDSM4T(vh_, st + 16384 + soff(ks * 16 + vR, d0 * 16 + vD));
                    MMAH16816(o_[2*d0],   A0,A1,A2,A3, vh_[0], vh_[1]);
                    MMAH16816(o_[2*d0],   L0,L1,L2,L3, vh_[0], vh_[1]);
                    MMAH16816(o_[2*d0+1], A0,A1,A2,A3, vh_[2], vh_[3]);
                    MMAH16816(o_[2*d0+1], L0,L1,L2,L3, vh_[2], vh_[3]);
                }
            }
        }
        __syncthreads();
    }

    // ---- epilogue: reduce l over quad, normalize, store ----
    lsum0 += __shfl_xor_sync(0xffffffffu, lsum0, 1);
    lsum0 += __shfl_xor_sync(0xffffffffu, lsum0, 2);
    lsum1 += __shfl_xor_sync(0xffffffffu, lsum1, 1);
    lsum1 += __shfl_xor_sync(0xffffffffu, lsum1, 2);
    float inv0 = 1.0f / lsum0;
    float inv1 = 1.0f / lsum1;
    size_t rbase = OFF_ATTN + ((size_t)bh * SS + row0) * DD;
    #pragma unroll
    for (int n2 = 0; n2 < 16; n2++) {
        int d = n2 * 8 + 2 * (l & 3);
        float2 a = {o_[n2][0] * inv0, o_[n2][1] * inv0};
        float2 b = {o_[n2][2] * inv1, o_[n2][3] * inv1};
        *(float2*)&out[rbase + d] = a;
        *(float2*)&out[rbase + 8 * DD + d] = b;
    }
}

// ---------------------------------------------------------------------------
// K top-k pipeline. Keys = (abs_bits << 32) | (4095 - s): abs desc, idx asc.
// ---------------------------------------------------------------------------
__global__ void kq_partial(const float* __restrict__ kr) {
    int bh = blockIdx.x, ch = blockIdx.y, d = threadIdx.x;
    unsigned long long a[17];
    #pragma unroll
    for (int i = 0; i < 17; i++) a[i] = 0ull;

    int s0 = ch * 128;
    const float* p = kr + ((size_t)bh * SS + s0) * DD + d;
    int ibeg = (ch == 0) ? 4 : 0;
    for (int i = ibeg; i < 128; i++) {
        float v = p[(size_t)i * DD];
        unsigned ab = __float_as_uint(fabsf(v));
        unsigned long long key = ((unsigned long long)ab << 32) | (unsigned)(4095 - (s0 + i));
        ins17(a, key);
    }
    unsigned long long* dst = g_pk + (((size_t)bh * DD + d) * 16 + ch) * 17;
    #pragma unroll
    for (int i = 0; i < 17; i++) dst[i] = a[i];
}

__global__ void kq_merge(const float* __restrict__ kr, float* __restrict__ out) {
    int bh = blockIdx.x, d = threadIdx.x;
    unsigned long long a[17];
    #pragma unroll
    for (int i = 0; i < 17; i++) a[i] = 0ull;

    const unsigned long long* pk = g_pk + ((size_t)bh * DD + d) * 16 * 17;
    for (int t = 0; t < 16 * 17; t++) ins17(a, pk[t]);

    float absmax = __uint_as_float((unsigned)(a[16] >> 32));
    float scale = fmaxf(absmax, 1e-8f) / 127.0f;
    out[OFF_KSCALE + (size_t)bh * DD + d] = scale;

    size_t sp = ((size_t)bh * DD + d) * 16;
    int idxs[16];
    #pragma unroll
    for (int i = 0; i < 16; i++) {
        int s = 4095 - (int)(unsigned)(a[i] & 0xFFFFFFFFull);
        idxs[i] = s;
        out[OFF_KSPI + sp + i] = (float)s;
        out[OFF_KSPV + sp + i] = kr[((size_t)bh * SS + s) * DD + d];
    }

    unsigned m[64];
    for (int w = 0; w < 64; w++) m[w] = 0u;
    #pragma unroll
    for (int i = 0; i < 16; i++) m[idxs[i] >> 5] |= (1u << (idxs[i] & 31));
    for (int w = 0; w < 64; w++)
        g_mask[((size_t)bh * 64 + w) * DD + d] = m[w];
}

__global__ __launch_bounds__(256)
void kq_write(const float* __restrict__ kr, float* __restrict__ out) {
    __shared__ unsigned smask[512];
    __shared__ float sscale[128];
    int bh = blockIdx.x, scn = blockIdx.y;
    int tid = threadIdx.x;

    for (int i = tid; i < 512; i += 256) {
        int w4 = i >> 7, d = i & 127;
        smask[i] = g_mask[((size_t)bh * 64 + scn * 4 + w4) * DD + d];
    }
    if (tid < 128) sscale[tid] = out[OFF_KSCALE + (size_t)bh * DD + tid];
    __syncthreads();

    for (int u = tid; u < 4096; u += 256) {
        int r = u >> 5, d4 = u & 31;
        int s = scn * 128 + r;
        size_t off = ((size_t)bh * SS + s) * DD + d4 * 4;
        float4 v = *(const float4*)(kr + off);
        int w4 = r >> 5;
        int bit = s & 31;
        float vv[4] = {v.x, v.y, v.z, v.w};
        float q[4];
        #pragma unroll
        for (int j = 0; j < 4; j++) {
            int dd = d4 * 4 + j;
            bool z = (s < 4) || ((smask[w4 * 128 + dd] >> bit) & 1u);
            if (z) {
                q[j] = 0.0f;
            } else {
                float r2 = rintf(vv[j] / sscale[dd]);
                q[j] = fminf(fmaxf(r2, -127.0f), 127.0f);
            }
        }
        float4 qo = {q[0], q[1], q[2], q[3]};
        *(float4*)&out[OFF_KQ + off] = qo;
    }
}

// ---------------------------------------------------------------------------
// V side: warp per token. top-5 of |v| over D=128 (abs desc, idx asc ties).
// ---------------------------------------------------------------------------
__global__ void vquant_kernel(const float* __restrict__ v, float* __restrict__ out) {
    int gwarp = (int)((blockIdx.x * (size_t)blockDim.x + threadIdx.x) >> 5);
    int lane = threadIdx.x & 31;
    if (gwarp >= BHN * SS) return;
    int s = gwarp & (SS - 1);

    const float* row = v + (size_t)gwarp * DD;
    float4 x = *(const float4*)(row + lane * 4);
    float vals[4] = {x.x, x.y, x.z, x.w};

    int tidx[4] = {0, 1, 2, 3};
    float tval[4] = {0.0f, 0.0f, 0.0f, 0.0f};
    float absmax = 0.0f;
    bool sink = (s < 4);

    if (!sink) {
        unsigned used = 0u;
        unsigned long long keys[4];
        #pragma unroll
        for (int i = 0; i < 4; i++) {
            unsigned ab = __float_as_uint(fabsf(vals[i]));
            keys[i] = ((unsigned long long)ab << 32) | (unsigned)(127 - (lane * 4 + i));
        }
        for (int rnd = 0; rnd < 5; rnd++) {
            unsigned long long best = 0ull;
            #pragma unroll
            for (int i = 0; i < 4; i++)
                if (!((used >> i) & 1u) && keys[i] > best) best = keys[i];
            #pragma unroll
            for (int off = 16; off >= 1; off >>= 1) {
                unsigned long long o2 = __shfl_xor_sync(0xffffffffu, best, off);
                if (o2 > best) best = o2;
            }
            int gidx = 127 - (int)(unsigned)(best & 0xffffffffull);
            float ab = __uint_as_float((unsigned)(best >> 32));
            int owner = gidx >> 2, slot = gidx & 3;
            if (lane == owner) used |= (1u << slot);
            if (rnd < 4) {
                float cand = (slot == 0) ? vals[0] : (slot == 1) ? vals[1]
                           : (slot == 2) ? vals[2] : vals[3];
                float sv = __shfl_sync(0xffffffffu, cand, owner);
                tidx[rnd] = gidx;
                tval[rnd] = sv;
            } else {
                absmax = ab;
            }
        }
    }

    float scale = fmaxf(absmax, 1e-8f) / 127.0f;

    float q[4];
    #pragma unroll
    for (int i = 0; i < 4; i++) {
        int gi = lane * 4 + i;
        bool zero = sink | (gi == tidx[0]) | (gi == tidx[1]) | (gi == tidx[2]) | (gi == tidx[3]);
        if (zero) {
            q[i] = 0.0f;
        } else {
            float r = rintf(vals[i] / scale);
            q[i] = fminf(fmaxf(r, -127.0f), 127.0f);
        }
    }
    float4 qo = {q[0], q[1], q[2], q[3]};
    *(float4*)&out[OFF_VQ + (size_t)gwarp * DD + lane * 4] = qo;

    if (lane == 0) {
        out[OFF_VSCALE + gwarp] = scale;
        #pragma unroll
        for (int t = 0; t < 4; t++) {
            out[OFF_VSPV + (size_t)gwarp * 4 + t] = tval[t];
            out[OFF_VSPI + (size_t)gwarp * 4 + t] = (float)tidx[t];
        }
    }
}

// ---------------------------------------------------------------------------
extern "C" void kernel_launch(void* const* d_in, const int* in_sizes, int n_in,
                              void* d_out, int out_size) {
    const float* q = (const float*)d_in[0];
    const float* k = (const float*)d_in[1];
    const float* v = (const float*)d_in[2];
    const int* pos = (const int*)d_in[3];
    float* out = (float*)d_out;

    float* krot; cudaGetSymbolAddress((void**)&krot, g_krot);
    uint4 *pqh, *pql, *pkb, *pvb;
    cudaGetSymbolAddress((void**)&pqh, g_qh);
    cudaGetSymbolAddress((void**)&pql, g_ql);
    cudaGetSymbolAddress((void**)&pkb, g_kb);
    cudaGetSymbolAddress((void**)&pvb, g_vb);

    // 1. inv_freq + cos/sin table
    invf_kernel<<<1, 64>>>();
    table_kernel<<<SS, 64>>>();

    // 2. Fused RoPE + fp16 planes (Q hi/lo, K) + krot f32
    rope_split_kernel<<<(BHN * SS * 8 + 255) / 256, 256>>>(q, k, pos);

    // 3. V fp16 plane
    v_split_kernel<<<(BHN * SS * 16 + 255) / 256, 256>>>(v);

    // 4. Attention (mma.sync fp16, 2x2-pass split, Q-in-regs, cp.async pipeline)
    {
        cudaFuncSetAttribute(attn_mma_kernel, cudaFuncAttributeMaxDynamicSharedMemorySize, SM_TOT);
        dim3 grid(16, BHN);
        attn_mma_kernel<<<grid, 256, SM_TOT>>>(pqh, pql, pkb, pvb, out);
    }

    // 5. K quant pipeline: partial top-17 -> merge -> quantize
    {
        dim3 gp(BHN, 16);
        kq_partial<<<gp, 128>>>(krot);
        kq_merge<<<BHN, 128>>>(krot, out);
        dim3 gw(BHN, 16);
        kq_write<<<gw, 256>>>(krot, out);
    }

    // 6. V quant + outliers
    {
        int warps = BHN * SS;
        int threads = 256;
        int blocks = (warps * 32 + threads - 1) / threads;
        vquant_kernel<<<blocks, threads>>>(v, out);
    }
}

// round 14
// speedup vs baseline: 8.6853x; 1.0322x over previous
#include <cuda_runtime.h>
#include <cuda_bf16.h>
#include <cuda_fp16.h>
#include <math.h>
#include <stdint.h>

// Problem dims
#define BB 2
#define HH 32
#define SS 2048
#define DD 128
#define BHN (BB*HH)

// Output layout (floats), concatenated in reference return order
#define OFF_ATTN   ((size_t)0)
#define OFF_KQ     ((size_t)16777216)
#define OFF_KSCALE ((size_t)33554432)
#define OFF_VQ     ((size_t)33562624)
#define OFF_VSCALE ((size_t)50339840)
#define OFF_KSPV   ((size_t)50470912)
#define OFF_KSPI   ((size_t)50601984)
#define OFF_VSPV   ((size_t)50733056)
#define OFF_VSPI   ((size_t)51257344)

// Scratch (device globals: no allocation allowed)
__device__ float g_krot[BB*HH*SS*DD];
__device__ float g_invf[64];
__device__ float g_cos[SS*64];
__device__ float g_sin[SS*64];
// fp16 planes, pre-swizzled rows of 256B (16 x 16B chunks, chunk ^= row&7)
__device__ uint4 g_qh[BHN*SS*16];   // fp16(q_rot) hi
__device__ uint4 g_ql[BHN*SS*16];   // fp16 residual of q_rot
__device__ uint4 g_kb[BHN*SS*16];   // fp16(k_rot), unsplit
__device__ uint4 g_vb[BHN*SS*16];   // fp16(v), unsplit
// K top-k pipeline scratch
__device__ unsigned long long g_pk[BHN*DD*16*17];   // partial top-17 keys
__device__ unsigned g_mask[BHN*64*DD];              // outlier bitmap [bh][w][d]

// ===========================================================================
// helpers
// ===========================================================================
__device__ __forceinline__ uint32_t smem_u32(const void* p) {
    uint32_t a;
    asm("{ .reg .u64 t; cvta.to.shared.u64 t, %1; cvt.u32.u64 %0, t; }"
        : "=r"(a) : "l"(p));
    return a;
}

// swizzled byte offset within a [rows][128 fp16] tile, 256B row pitch
__device__ __forceinline__ int soff(int r, int d) {
    return r * 256 + ((((d >> 3) ^ (r & 7)) & 15) << 4) + ((d & 7) << 1);
}

#define LDSM4(r, a) \
    asm volatile("ldmatrix.sync.aligned.m8n8.x4.shared.b16 {%0,%1,%2,%3}, [%4];" \
        : "=r"((r)[0]), "=r"((r)[1]), "=r"((r)[2]), "=r"((r)[3]) : "r"(a))
#define LDSM4T(r, a) \
    asm volatile("ldmatrix.sync.aligned.m8n8.x4.trans.shared.b16 {%0,%1,%2,%3}, [%4];" \
        : "=r"((r)[0]), "=r"((r)[1]), "=r"((r)[2]), "=r"((r)[3]) : "r"(a))

#define MMAH16816(c, a0,a1,a2,a3, b0,b1) \
    asm volatile("mma.sync.aligned.m16n8k16.row.col.f32.f16.f16.f32 " \
        "{%0,%1,%2,%3}, {%4,%5,%6,%7}, {%8,%9}, {%0,%1,%2,%3};" \
        : "+f"((c)[0]), "+f"((c)[1]), "+f"((c)[2]), "+f"((c)[3]) \
        : "r"(a0), "r"(a1), "r"(a2), "r"(a3), "r"(b0), "r"(b1))

#define CP_ASYNC16(dst, src) \
    asm volatile("cp.async.cg.shared.global [%0], [%1], 16;" \
        :: "r"(dst), "l"(src) : "memory")
#define CP_COMMIT() asm volatile("cp.async.commit_group;" ::: "memory")
#define CP_WAIT0()  asm volatile("cp.async.wait_group 0;" ::: "memory")
#define CP_WAIT1()  asm volatile("cp.async.wait_group 1;" ::: "memory")

__device__ __forceinline__ float ex2f(float x) {
    float y;
    asm("ex2.approx.f32 %0, %1;" : "=f"(y) : "f"(x));
    return y;
}

// pack two floats to fp16x2 (rn)
__device__ __forceinline__ uint32_t pk2h(float a, float b) {
    __half ha = __float2half_rn(a);
    __half hb = __float2half_rn(b);
    return ((uint32_t)__half_as_ushort(hb) << 16) | (uint32_t)__half_as_ushort(ha);
}

__device__ __forceinline__ uint4 pack8h(const float* v) {
    uint4 r;
    r.x = pk2h(v[0], v[1]);
    r.y = pk2h(v[2], v[3]);
    r.z = pk2h(v[4], v[5]);
    r.w = pk2h(v[6], v[7]);
    return r;
}

// fp16 split: hi = fp16(a,b), lo = fp16 residuals
__device__ __forceinline__ uint32_t hsplit2(float a, float b, uint32_t& lo) {
    __half ha = __float2half_rn(a);
    __half hb = __float2half_rn(b);
    float ra = a - __half2float(ha);
    float rb = b - __half2float(hb);
    __half la = __float2half_rn(ra);
    __half lb = __float2half_rn(rb);
    lo = ((uint32_t)__half_as_ushort(lb) << 16) | (uint32_t)__half_as_ushort(la);
    return ((uint32_t)__half_as_ushort(hb) << 16) | (uint32_t)__half_as_ushort(ha);
}

__device__ __forceinline__ void split8h(const float* v, uint4& hi, uint4& lo) {
    uint32_t l0, l1, l2, l3;
    hi.x = hsplit2(v[0], v[1], l0);
    hi.y = hsplit2(v[2], v[3], l1);
    hi.z = hsplit2(v[4], v[5], l2);
    hi.w = hsplit2(v[6], v[7], l3);
    lo.x = l0; lo.y = l1; lo.z = l2; lo.w = l3;
}

// Register-resident guarded top-17 insert (descending u64 keys, all static idx).
__device__ __forceinline__ void ins17(unsigned long long* a, unsigned long long key) {
    if (key > a[16]) {
        #pragma unroll
        for (int j = 16; j > 0; j--) {
            unsigned long long pj = a[j-1];
            a[j] = (key > pj) ? pj : ((key > a[j]) ? key : a[j]);
        }
        if (key > a[0]) a[0] = key;
    }
}

// ---------------------------------------------------------------------------
// inv_freq: 64 double pow calls only (bit-identical to reference).
// ---------------------------------------------------------------------------
__global__ void invf_kernel() {
    int j = threadIdx.x;
    double e = (double)(2 * j) / 128.0;
    double p = pow(10000.0, e);
    float pf = (float)p;
    g_invf[j] = 1.0f / pf;
}

// ---------------------------------------------------------------------------
// Custom double sincos (Cody-Waite + fdlibm polys); bit-matches libm at f32.
// ---------------------------------------------------------------------------
__device__ __forceinline__ void dsincos_f(float angf, float* cs, float* sn) {
    const double pio2_1  = 1.57079632673412561417e+00;
    const double pio2_1t = 6.07710050650619224932e-11;
    double x = (double)angf;
    double kd = rint(x * 6.36619772367581382433e-01);
    double r = x - kd * pio2_1;
    r = r - kd * pio2_1t;
    double z = r * r;
    double ps = 1.58969099521155010221e-10;
    ps = ps * z + -2.50507602534068634195e-08;
    ps = ps * z +  2.75573137070700676789e-06;
    ps = ps * z + -1.98412698298579493134e-04;
    ps = ps * z +  8.33333333332248946124e-03;
    ps = ps * z + -1.66666666666666324348e-01;
    double s = r + r * z * ps;
    double pc = -1.13596475577881948265e-11;
    pc = pc * z +  2.08757232129817482790e-09;
    pc = pc * z + -2.75573143513906633035e-07;
    pc = pc * z +  2.48015872894767294178e-05;
    pc = pc * z + -1.38888888888741095749e-03;
    pc = pc * z +  4.16666666666666019037e-02;
    double c = 1.0 + z * (-0.5 + z * pc);
    int q = ((int)kd) & 3;
    double sv, cv;
    if (q == 0)      { sv = s;  cv = c;  }
    else if (q == 1) { sv = c;  cv = -s; }
    else if (q == 2) { sv = -s; cv = -c; }
    else             { sv = -c; cv = s;  }
    *sn = (float)sv;
    *cs = (float)cv;
}

__global__ void table_kernel() {
    int s = blockIdx.x;
    int j = threadIdx.x;
    float ang = __fmul_rn((float)s, g_invf[j]);
    float c, sn;
    dsincos_f(ang, &c, &sn);
    g_cos[s * 64 + j] = c;
    g_sin[s * 64 + j] = sn;
}

// ---------------------------------------------------------------------------
// Fused RoPE + fp16 planes (Q split hi/lo, K unsplit) + krot f32.
// ---------------------------------------------------------------------------
__global__ void rope_split_kernel(const float* __restrict__ q, const float* __restrict__ k,
                                  const int* __restrict__ pos_ids) {
    int idx = blockIdx.x * 256 + threadIdx.x;
    if (idx >= BHN * SS * 8) return;
    int c = idx & 7;
    int s = (idx >> 3) & 2047;
    int bh = idx >> 14;
    int b = bh >> 5;
    int pos = pos_ids[b * SS + s];
    int d0 = c * 8;
    size_t rb = ((size_t)bh * SS + s) * DD;

    float xq[8], yq[8], xk[8], yk[8], cs[8], sn[8];
    *(float4*)&xq[0] = *(const float4*)&q[rb + d0];
    *(float4*)&xq[4] = *(const float4*)&q[rb + d0 + 4];
    *(float4*)&yq[0] = *(const float4*)&q[rb + d0 + 64];
    *(float4*)&yq[4] = *(const float4*)&q[rb + d0 + 68];
    *(float4*)&xk[0] = *(const float4*)&k[rb + d0];
    *(float4*)&xk[4] = *(const float4*)&k[rb + d0 + 4];
    *(float4*)&yk[0] = *(const float4*)&k[rb + d0 + 64];
    *(float4*)&yk[4] = *(const float4*)&k[rb + d0 + 68];
    #pragma unroll
    for (int i = 0; i < 8; i++) {
        cs[i] = g_cos[pos * 64 + d0 + i];
        sn[i] = g_sin[pos * 64 + d0 + i];
    }

    float loq[8], upq[8], lok[8], upk[8];
    #pragma unroll
    for (int i = 0; i < 8; i++) {
        loq[i] = __fsub_rn(__fmul_rn(xq[i], cs[i]), __fmul_rn(yq[i], sn[i]));
        upq[i] = __fadd_rn(__fmul_rn(yq[i], cs[i]), __fmul_rn(xq[i], sn[i]));
        lok[i] = __fsub_rn(__fmul_rn(xk[i], cs[i]), __fmul_rn(yk[i], sn[i]));
        upk[i] = __fadd_rn(__fmul_rn(yk[i], cs[i]), __fmul_rn(xk[i], sn[i]));
    }

    *(float4*)&g_krot[rb + d0]      = *(float4*)&lok[0];
    *(float4*)&g_krot[rb + d0 + 4]  = *(float4*)&lok[4];
    *(float4*)&g_krot[rb + d0 + 64] = *(float4*)&upk[0];
    *(float4*)&g_krot[rb + d0 + 68] = *(float4*)&upk[4];

    size_t rowb = ((size_t)bh * SS + s) * 16;
    int pcl = c ^ (s & 7);
    int pcu = 8 + pcl;
    uint4 hi, lo;
    split8h(loq, hi, lo); g_qh[rowb + pcl] = hi; g_ql[rowb + pcl] = lo;
    split8h(upq, hi, lo); g_qh[rowb + pcu] = hi; g_ql[rowb + pcu] = lo;
    g_kb[rowb + pcl] = pack8h(lok);
    g_kb[rowb + pcu] = pack8h(upk);
}

// ---------------------------------------------------------------------------
// V fp16 plane (unsplit).
// ---------------------------------------------------------------------------
__global__ void v_split_kernel(const float* __restrict__ v) {
    int idx = blockIdx.x * 256 + threadIdx.x;
    if (idx >= BHN * SS * 16) return;
    int c = idx & 15;
    int s = (idx >> 4) & 2047;
    int bh = idx >> 15;
    size_t rb = ((size_t)bh * SS + s) * DD;
    float x[8];
    *(float4*)&x[0] = *(const float4*)&v[rb + c * 8];
    *(float4*)&x[4] = *(const float4*)&v[rb + c * 8 + 4];
    size_t rowb = ((size_t)bh * SS + s) * 16;
    int pc = c ^ (s & 7);
    g_vb[rowb + pc] = pack8h(x);
}

// ---------------------------------------------------------------------------
// Flash attention, mma.sync m16n8k16 fp16, 2x2-pass split (Q,P split; K,V not).
// BM=64 (4 warps x M=16), 128 threads -> 2 independent blocks/SM (RF-limited
// occupancy doubles vs 256-thr version; no shared barrier between the two
// blocks so MMA and softmax/convert phases overlap across blocks).
// Smem: 2 stages x 32KB (K 16K, V 16K); Q hi/lo (16K+16K) staged first.
// ---------------------------------------------------------------------------
#define STG 32768
#define SM_TOT 65536

__global__ __launch_bounds__(128, 2)
void attn_mma_kernel(const uint4* __restrict__ pqh, const uint4* __restrict__ pql,
                     const uint4* __restrict__ pkb, const uint4* __restrict__ pvb,
                     float* __restrict__ out) {
    extern __shared__ char smc[];
    const int tid = threadIdx.x;
    const int w = tid >> 5, l = tid & 31;
    const int qb = 31 - (int)blockIdx.x;     // heavy blocks first
    const int bh = blockIdx.y;
    const uint32_t sb = smem_u32(smc);

    const int rowmin = qb * 64 + w * 16;
    const int row0 = rowmin + (l >> 2);
    const int aR = ((l >> 3) & 1) * 8 + (l & 7);
    const int aK = ((l >> 4) & 1) * 8;
    const int bR = ((l >> 4) & 1) * 8 + (l & 7);
    const int bK = ((l >> 3) & 1) * 8;
    const int vR = ((l >> 3) & 1) * 8 + (l & 7);
    const int vD = ((l >> 4) & 1) * 8;
    const float sc = 0.088388347648318447f * 1.4426950408889634f;
    const int nt = qb + 1;

    // ---- Stage Q hi/lo into smem (cp.async), hoist fragments to registers ----
    {
        size_t qsrc = ((size_t)bh * SS + (size_t)qb * 64) * 16;
        #pragma unroll
        for (int j = 0; j < 8; j++) {
            int i = tid + j * 128;     // 0..1023
            CP_ASYNC16(sb + i * 16, pqh + qsrc + i);
            CP_ASYNC16(sb + 16384 + i * 16, pql + qsrc + i);
        }
        CP_COMMIT();
        CP_WAIT0();
    }
    __syncthreads();

    uint32_t qh[8][4], ql[8][4];
    #pragma unroll
    for (int ks = 0; ks < 8; ks++) {
        uint32_t qaddr = sb + soff(w * 16 + aR, ks * 16 + aK);
        LDSM4(qh[ks], qaddr);
        LDSM4(ql[ks], qaddr + 16384);
    }
    __syncthreads();   // Q regs captured; smem recycled for K/V stages

    // ---- Prefetch tile 0 into stage 0 ----
    {
        size_t src = (size_t)bh * SS * 16;
        #pragma unroll
        for (int j = 0; j < 8; j++) {
            int i = tid + j * 128;     // 0..1023
            CP_ASYNC16(sb + i * 16,         pkb + src + i);
            CP_ASYNC16(sb + 16384 + i * 16, pvb + src + i);
        }
        CP_COMMIT();
    }

    float o_[16][4];
    #pragma unroll
    for (int i = 0; i < 16; i++)
        #pragma unroll
        for (int j = 0; j < 4; j++) o_[i][j] = 0.0f;
    float lsum0 = 0.0f, lsum1 = 0.0f;

    for (int t = 0; t < nt; t++) {
        if (t + 1 < nt) {
            uint32_t st = sb + ((t + 1) & 1) * STG;
            size_t src = ((size_t)bh * SS + (size_t)(t + 1) * 64) * 16;
            #pragma unroll
            for (int j = 0; j < 8; j++) {
                int i = tid + j * 128;
                CP_ASYNC16(st + i * 16,         pkb + src + i);
                CP_ASYNC16(st + 16384 + i * 16, pvb + src + i);
            }
            CP_COMMIT();
            CP_WAIT1();
        } else {
            CP_WAIT0();
        }
        __syncthreads();

        const uint32_t st = sb + (t & 1) * STG;

        // ---- S = Qhi*K + Qlo*K ----
        float s_[8][4];
        #pragma unroll
        for (int i = 0; i < 8; i++)
            #pragma unroll
            for (int j = 0; j < 4; j++) s_[i][j] = 0.0f;

        #pragma unroll
        for (int ks = 0; ks < 8; ks++) {
            #pragma unroll
            for (int n0 = 0; n0 < 4; n0++) {
                uint32_t kh_[4];
                LDSM4(kh_, st + soff(n0 * 16 + bR, ks * 16 + bK));
                MMAH16816(s_[2*n0],   qh[ks][0],qh[ks][1],qh[ks][2],qh[ks][3], kh_[0], kh_[1]);
                MMAH16816(s_[2*n0],   ql[ks][0],ql[ks][1],ql[ks][2],ql[ks][3], kh_[0], kh_[1]);
                MMAH16816(s_[2*n0+1], qh[ks][0],qh[ks][1],qh[ks][2],qh[ks][3], kh_[2], kh_[3]);
                MMAH16816(s_[2*n0+1], ql[ks][0],ql[ks][1],ql[ks][2],ql[ks][3], kh_[2], kh_[3]);
            }
        }

        // ---- softmax (no rescale), build split-fp16 P fragments in regs ----
        const bool needmask = (64 * t + 63 > rowmin);
        uint32_t phi[8][2], plo[8][2];
        const int colb = 64 * t + 2 * (l & 3);
        #pragma unroll
        for (int n2 = 0; n2 < 8; n2++) {
            float p0 = ex2f(s_[n2][0] * sc);
            float p1 = ex2f(s_[n2][1] * sc);
            float p2 = ex2f(s_[n2][2] * sc);
            float p3 = ex2f(s_[n2][3] * sc);
            if (needmask) {
                int c0 = colb + 8 * n2;
                if (c0     > row0)     p0 = 0.0f;
                if (c0 + 1 > row0)     p1 = 0.0f;
                if (c0     > row0 + 8) p2 = 0.0f;
                if (c0 + 1 > row0 + 8) p3 = 0.0f;
            }
            lsum0 += p0 + p1;
            lsum1 += p2 + p3;
            uint32_t t0, t1;
            phi[n2][0] = hsplit2(p0, p1, t0); plo[n2][0] = t0;
            phi[n2][1] = hsplit2(p2, p3, t1); plo[n2][1] = t1;
        }

        // ---- O += Phi*V + Plo*V ----
        #pragma unroll
        for (int ks = 0; ks < 4; ks++) {
            uint32_t A0 = phi[2*ks][0], A1 = phi[2*ks][1];
            uint32_t A2 = phi[2*ks+1][0], A3 = phi[2*ks+1][1];
            uint32_t L0 = plo[2*ks][0], L1 = plo[2*ks][1];
            uint32_t L2 = plo[2*ks+1][0], L3 = plo[2*ks+1][1];
            #pragma unroll
            for (int d0 = 0; d0 < 8; d0++) {
                uint32_t vh_[4];
                LDSM4T(vh_, st + 16384 + soff(ks * 16 + vR, d0 * 16 + vD));
                MMAH16816(o_[2*d0],   A0,A1,A2,A3, vh_[0], vh_[1]);
                MMAH16816(o_[2*d0],   L0,L1,L2,L3, vh_[0], vh_[1]);
                MMAH16816(o_[2*d0+1], A0,A1,A2,A3, vh_[2], vh_[3]);
                MMAH16816(o_[2*d0+1], L0,L1,L2,L3, vh_[2], vh_[3]);
            }
        }
        __syncthreads();
    }

    // ---- epilogue: reduce l over quad, normalize, store ----
    lsum0 += __shfl_xor_sync(0xffffffffu, lsum0, 1);
    lsum0 += __shfl_xor_sync(0xffffffffu, lsum0, 2);
    lsum1 += __shfl_xor_sync(0xffffffffu, lsum1, 1);
    lsum1 += __shfl_xor_sync(0xffffffffu, lsum1, 2);
    float inv0 = 1.0f / lsum0;
    float inv1 = 1.0f / lsum1;
    size_t rbase = OFF_ATTN + ((size_t)bh * SS + row0) * DD;
    #pragma unroll
    for (int n2 = 0; n2 < 16; n2++) {
        int d = n2 * 8 + 2 * (l & 3);
        float2 a = {o_[n2][0] * inv0, o_[n2][1] * inv0};
        float2 b = {o_[n2][2] * inv1, o_[n2][3] * inv1};
        *(float2*)&out[rbase + d] = a;
        *(float2*)&out[rbase + 8 * DD + d] = b;
    }
}

// ---------------------------------------------------------------------------
// K top-k pipeline. Keys = (abs_bits << 32) | (4095 - s): abs desc, idx asc.
// ---------------------------------------------------------------------------
__global__ void kq_partial(const float* __restrict__ kr) {
    int bh = blockIdx.x, ch = blockIdx.y, d = threadIdx.x;
    unsigned long long a[17];
    #pragma unroll
    for (int i = 0; i < 17; i++) a[i] = 0ull;

    int s0 = ch * 128;
    const float* p = kr + ((size_t)bh * SS + s0) * DD + d;
    int ibeg = (ch == 0) ? 4 : 0;
    for (int i = ibeg; i < 128; i++) {
        float v = p[(size_t)i * DD];
        unsigned ab = __float_as_uint(fabsf(v));
        unsigned long long key = ((unsigned long long)ab << 32) | (unsigned)(4095 - (s0 + i));
        ins17(a, key);
    }
    unsigned long long* dst = g_pk + (((size_t)bh * DD + d) * 16 + ch) * 17;
    #pragma unroll
    for (int i = 0; i < 17; i++) dst[i] = a[i];
}

__global__ void kq_merge(const float* __restrict__ kr, float* __restrict__ out) {
    int bh = blockIdx.x, d = threadIdx.x;
    unsigned long long a[17];
    #pragma unroll
    for (int i = 0; i < 17; i++) a[i] = 0ull;

    const unsigned long long* pk = g_pk + ((size_t)bh * DD + d) * 16 * 17;
    for (int t = 0; t < 16 * 17; t++) ins17(a, pk[t]);

    float absmax = __uint_as_float((unsigned)(a[16] >> 32));
    float scale = fmaxf(absmax, 1e-8f) / 127.0f;
    out[OFF_KSCALE + (size_t)bh * DD + d] = scale;

    size_t sp = ((size_t)bh * DD + d) * 16;
    int idxs[16];
    #pragma unroll
    for (int i = 0; i < 16; i++) {
        int s = 4095 - (int)(unsigned)(a[i] & 0xFFFFFFFFull);
        idxs[i] = s;
        out[OFF_KSPI + sp + i] = (float)s;
        out[OFF_KSPV + sp + i] = kr[((size_t)bh * SS + s) * DD + d];
    }

    unsigned m[64];
    for (int w = 0; w < 64; w++) m[w] = 0u;
    #pragma unroll
    for (int i = 0; i < 16; i++) m[idxs[i] >> 5] |= (1u << (idxs[i] & 31));
    for (int w = 0; w < 64; w++)
        g_mask[((size_t)bh * 64 + w) * DD + d] = m[w];
}

__global__ __launch_bounds__(256)
void kq_write(const float* __restrict__ kr, float* __restrict__ out) {
    __shared__ unsigned smask[512];
    __shared__ float sscale[128];
    int bh = blockIdx.x, scn = blockIdx.y;
    int tid = threadIdx.x;

    for (int i = tid; i < 512; i += 256) {
        int w4 = i >> 7, d = i & 127;
        smask[i] = g_mask[((size_t)bh * 64 + scn * 4 + w4) * DD + d];
    }
    if (tid < 128) sscale[tid] = out[OFF_KSCALE + (size_t)bh * DD + tid];
    __syncthreads();

    for (int u = tid; u < 4096; u += 256) {
        int r = u >> 5, d4 = u & 31;
        int s = scn * 128 + r;
        size_t off = ((size_t)bh * SS + s) * DD + d4 * 4;
        float4 v = *(const float4*)(kr + off);
        int w4 = r >> 5;
        int bit = s & 31;
        float vv[4] = {v.x, v.y, v.z, v.w};
        float q[4];
        #pragma unroll
        for (int j = 0; j < 4; j++) {
            int dd = d4 * 4 + j;
            bool z = (s < 4) || ((smask[w4 * 128 + dd] >> bit) & 1u);
            if (z) {
                q[j] = 0.0f;
            } else {
                float r2 = rintf(vv[j] / sscale[dd]);
                q[j] = fminf(fmaxf(r2, -127.0f), 127.0f);
            }
        }
        float4 qo = {q[0], q[1], q[2], q[3]};
        *(float4*)&out[OFF_KQ + off] = qo;
    }
}

// ---------------------------------------------------------------------------
// V side: warp per token. top-5 of |v| over D=128 (abs desc, idx asc ties).
// ---------------------------------------------------------------------------
__global__ void vquant_kernel(const float* __restrict__ v, float* __restrict__ out) {
    int gwarp = (int)((blockIdx.x * (size_t)blockDim.x + threadIdx.x) >> 5);
    int lane = threadIdx.x & 31;
    if (gwarp >= BHN * SS) return;
    int s = gwarp & (SS - 1);

    const float* row = v + (size_t)gwarp * DD;
    float4 x = *(const float4*)(row + lane * 4);
    float vals[4] = {x.x, x.y, x.z, x.w};

    int tidx[4] = {0, 1, 2, 3};
    float tval[4] = {0.0f, 0.0f, 0.0f, 0.0f};
    float absmax = 0.0f;
    bool sink = (s < 4);

    if (!sink) {
        unsigned used = 0u;
        unsigned long long keys[4];
        #pragma unroll
        for (int i = 0; i < 4; i++) {
            unsigned ab = __float_as_uint(fabsf(vals[i]));
            keys[i] = ((unsigned long long)ab << 32) | (unsigned)(127 - (lane * 4 + i));
        }
        for (int rnd = 0; rnd < 5; rnd++) {
            unsigned long long best = 0ull;
            #pragma unroll
            for (int i = 0; i < 4; i++)
                if (!((used >> i) & 1u) && keys[i] > best) best = keys[i];
            #pragma unroll
            for (int off = 16; off >= 1; off >>= 1) {
                unsigned long long o2 = __shfl_xor_sync(0xffffffffu, best, off);
                if (o2 > best) best = o2;
            }
            int gidx = 127 - (int)(unsigned)(best & 0xffffffffull);
            float ab = __uint_as_float((unsigned)(best >> 32));
            int owner = gidx >> 2, slot = gidx & 3;
            if (lane == owner) used |= (1u << slot);
            if (rnd < 4) {
                float cand = (slot == 0) ? vals[0] : (slot == 1) ? vals[1]
                           : (slot == 2) ? vals[2] : vals[3];
                float sv = __shfl_sync(0xffffffffu, cand, owner);
                tidx[rnd] = gidx;
                tval[rnd] = sv;
            } else {
                absmax = ab;
            }
        }
    }

    float scale = fmaxf(absmax, 1e-8f) / 127.0f;

    float q[4];
    #pragma unroll
    for (int i = 0; i < 4; i++) {
        int gi = lane * 4 + i;
        bool zero = sink | (gi == tidx[0]) | (gi == tidx[1]) | (gi == tidx[2]) | (gi == tidx[3]);
        if (zero) {
            q[i] = 0.0f;
        } else {
            float r = rintf(vals[i] / scale);
            q[i] = fminf(fmaxf(r, -127.0f), 127.0f);
        }
    }
    float4 qo = {q[0], q[1], q[2], q[3]};
    *(float4*)&out[OFF_VQ + (size_t)gwarp * DD + lane * 4] = qo;

    if (lane == 0) {
        out[OFF_VSCALE + gwarp] = scale;
        #pragma unroll
        for (int t = 0; t < 4; t++) {
            out[OFF_VSPV + (size_t)gwarp * 4 + t] = tval[t];
            out[OFF_VSPI + (size_t)gwarp * 4 + t] = (float)tidx[t];
        }
    }
}

// ---------------------------------------------------------------------------
extern "C" void kernel_launch(void* const* d_in, const int* in_sizes, int n_in,
                              void* d_out, int out_size) {
    const float* q = (const float*)d_in[0];
    const float* k = (const float*)d_in[1];
    const float* v = (const float*)d_in[2];
    const int* pos = (const int*)d_in[3];
    float* out = (float*)d_out;

    float* krot; cudaGetSymbolAddress((void**)&krot, g_krot);
    uint4 *pqh, *pql, *pkb, *pvb;
    cudaGetSymbolAddress((void**)&pqh, g_qh);
    cudaGetSymbolAddress((void**)&pql, g_ql);
    cudaGetSymbolAddress((void**)&pkb, g_kb);
    cudaGetSymbolAddress((void**)&pvb, g_vb);

    // 1. inv_freq + cos/sin table
    invf_kernel<<<1, 64>>>();
    table_kernel<<<SS, 64>>>();

    // 2. Fused RoPE + fp16 planes (Q hi/lo, K) + krot f32
    rope_split_kernel<<<(BHN * SS * 8 + 255) / 256, 256>>>(q, k, pos);

    // 3. V fp16 plane
    v_split_kernel<<<(BHN * SS * 16 + 255) / 256, 256>>>(v);

    // 4. Attention (mma.sync fp16, 2x2-pass split, BM=64, 2 blocks/SM)
    {
        cudaFuncSetAttribute(attn_mma_kernel, cudaFuncAttributeMaxDynamicSharedMemorySize, SM_TOT);
        dim3 grid(32, BHN);
        attn_mma_kernel<<<grid, 128, SM_TOT>>>(pqh, pql, pkb, pvb, out);
    }

    // 5. K quant pipeline: partial top-17 -> merge -> quantize
    {
        dim3 gp(BHN, 16);
        kq_partial<<<gp, 128>>>(krot);
        kq_merge<<<BHN, 128>>>(krot, out);
        dim3 gw(BHN, 16);
        kq_write<<<gw, 256>>>(krot, out);
    }

    // 6. V quant + outliers
    {
        int warps = BHN * SS;
        int threads = 256;
        int blocks = (warps * 32 + threads - 1) / threads;
        vquant_kernel<<<blocks, threads>>>(v, out);
    }
}

// round 15
// speedup vs baseline: 8.9889x; 1.0350x over previous
#include <cuda_runtime.h>
#include <cuda_bf16.h>
#include <cuda_fp16.h>
#include <math.h>
#include <stdint.h>

// Problem dims
#define BB 2
#define HH 32
#define SS 2048
#define DD 128
#define BHN (BB*HH)

// Output layout (floats), concatenated in reference return order
#define OFF_ATTN   ((size_t)0)
#define OFF_KQ     ((size_t)16777216)
#define OFF_KSCALE ((size_t)33554432)
#define OFF_VQ     ((size_t)33562624)
#define OFF_VSCALE ((size_t)50339840)
#define OFF_KSPV   ((size_t)50470912)
#define OFF_KSPI   ((size_t)50601984)
#define OFF_VSPV   ((size_t)50733056)
#define OFF_VSPI   ((size_t)51257344)

// Scratch (device globals: no allocation allowed)
__device__ float g_krot[BB*HH*SS*DD];
__device__ float g_invf[64];
__device__ float g_cos[SS*64];
__device__ float g_sin[SS*64];
// fp16 planes, pre-swizzled rows of 256B (16 x 16B chunks, chunk ^= row&7)
__device__ uint4 g_qb[BHN*SS*16];   // fp16(q_rot)
__device__ uint4 g_kb[BHN*SS*16];   // fp16(k_rot)
__device__ uint4 g_vb[BHN*SS*16];   // fp16(v)
// K top-k pipeline scratch
__device__ unsigned long long g_pk[BHN*DD*16*17];   // partial top-17 keys
__device__ unsigned g_mask[BHN*64*DD];              // outlier bitmap [bh][w][d]

// Mega-kernel grid layout
#define NB_ATTN 2048
#define NB_KQP  1024
#define NB_VQ   512
#define NB_TOT  (NB_ATTN + NB_KQP + NB_VQ)

// ===========================================================================
// helpers
// ===========================================================================
__device__ __forceinline__ uint32_t smem_u32(const void* p) {
    uint32_t a;
    asm("{ .reg .u64 t; cvta.to.shared.u64 t, %1; cvt.u32.u64 %0, t; }"
        : "=r"(a) : "l"(p));
    return a;
}

// swizzled byte offset within a [rows][128 fp16] tile, 256B row pitch
__device__ __forceinline__ int soff(int r, int d) {
    return r * 256 + ((((d >> 3) ^ (r & 7)) & 15) << 4) + ((d & 7) << 1);
}

#define LDSM4(r, a) \
    asm volatile("ldmatrix.sync.aligned.m8n8.x4.shared.b16 {%0,%1,%2,%3}, [%4];" \
        : "=r"((r)[0]), "=r"((r)[1]), "=r"((r)[2]), "=r"((r)[3]) : "r"(a))
#define LDSM4T(r, a) \
    asm volatile("ldmatrix.sync.aligned.m8n8.x4.trans.shared.b16 {%0,%1,%2,%3}, [%4];" \
        : "=r"((r)[0]), "=r"((r)[1]), "=r"((r)[2]), "=r"((r)[3]) : "r"(a))

#define MMAH16816(c, a0,a1,a2,a3, b0,b1) \
    asm volatile("mma.sync.aligned.m16n8k16.row.col.f32.f16.f16.f32 " \
        "{%0,%1,%2,%3}, {%4,%5,%6,%7}, {%8,%9}, {%0,%1,%2,%3};" \
        : "+f"((c)[0]), "+f"((c)[1]), "+f"((c)[2]), "+f"((c)[3]) \
        : "r"(a0), "r"(a1), "r"(a2), "r"(a3), "r"(b0), "r"(b1))

#define CP_ASYNC16(dst, src) \
    asm volatile("cp.async.cg.shared.global [%0], [%1], 16;" \
        :: "r"(dst), "l"(src) : "memory")
#define CP_COMMIT() asm volatile("cp.async.commit_group;" ::: "memory")
#define CP_WAIT0()  asm volatile("cp.async.wait_group 0;" ::: "memory")
#define CP_WAIT1()  asm volatile("cp.async.wait_group 1;" ::: "memory")

__device__ __forceinline__ float ex2f(float x) {
    float y;
    asm("ex2.approx.f32 %0, %1;" : "=f"(y) : "f"(x));
    return y;
}

// pack two floats to fp16x2 (rn)
__device__ __forceinline__ uint32_t pk2h(float a, float b) {
    __half ha = __float2half_rn(a);
    __half hb = __float2half_rn(b);
    return ((uint32_t)__half_as_ushort(hb) << 16) | (uint32_t)__half_as_ushort(ha);
}

__device__ __forceinline__ uint4 pack8h(const float* v) {
    uint4 r;
    r.x = pk2h(v[0], v[1]);
    r.y = pk2h(v[2], v[3]);
    r.z = pk2h(v[4], v[5]);
    r.w = pk2h(v[6], v[7]);
    return r;
}

// Register-resident guarded top-17 insert (descending u64 keys, all static idx).
__device__ __forceinline__ void ins17(unsigned long long* a, unsigned long long key) {
    if (key > a[16]) {
        #pragma unroll
        for (int j = 16; j > 0; j--) {
            unsigned long long pj = a[j-1];
            a[j] = (key > pj) ? pj : ((key > a[j]) ? key : a[j]);
        }
        if (key > a[0]) a[0] = key;
    }
}

// ---------------------------------------------------------------------------
// inv_freq: 64 double pow calls only (bit-identical to reference).
// ---------------------------------------------------------------------------
__global__ void invf_kernel() {
    int j = threadIdx.x;
    double e = (double)(2 * j) / 128.0;
    double p = pow(10000.0, e);
    float pf = (float)p;
    g_invf[j] = 1.0f / pf;
}

// ---------------------------------------------------------------------------
// Custom double sincos (Cody-Waite + fdlibm polys); bit-matches libm at f32.
// ---------------------------------------------------------------------------
__device__ __forceinline__ void dsincos_f(float angf, float* cs, float* sn) {
    const double pio2_1  = 1.57079632673412561417e+00;
    const double pio2_1t = 6.07710050650619224932e-11;
    double x = (double)angf;
    double kd = rint(x * 6.36619772367581382433e-01);
    double r = x - kd * pio2_1;
    r = r - kd * pio2_1t;
    double z = r * r;
    double ps = 1.58969099521155010221e-10;
    ps = ps * z + -2.50507602534068634195e-08;
    ps = ps * z +  2.75573137070700676789e-06;
    ps = ps * z + -1.98412698298579493134e-04;
    ps = ps * z +  8.33333333332248946124e-03;
    ps = ps * z + -1.66666666666666324348e-01;
    double s = r + r * z * ps;
    double pc = -1.13596475577881948265e-11;
    pc = pc * z +  2.08757232129817482790e-09;
    pc = pc * z + -2.75573143513906633035e-07;
    pc = pc * z +  2.48015872894767294178e-05;
    pc = pc * z + -1.38888888888741095749e-03;
    pc = pc * z +  4.16666666666666019037e-02;
    double c = 1.0 + z * (-0.5 + z * pc);
    int q = ((int)kd) & 3;
    double sv, cv;
    if (q == 0)      { sv = s;  cv = c;  }
    else if (q == 1) { sv = c;  cv = -s; }
    else if (q == 2) { sv = -s; cv = -c; }
    else             { sv = -c; cv = s;  }
    *sn = (float)sv;
    *cs = (float)cv;
}

__global__ void table_kernel() {
    int s = blockIdx.x;
    int j = threadIdx.x;
    float ang = __fmul_rn((float)s, g_invf[j]);
    float c, sn;
    dsincos_f(ang, &c, &sn);
    g_cos[s * 64 + j] = c;
    g_sin[s * 64 + j] = sn;
}

// ---------------------------------------------------------------------------
// Fused RoPE + fp16 planes (Q, K unsplit) + krot f32.
// ---------------------------------------------------------------------------
__global__ void rope_split_kernel(const float* __restrict__ q, const float* __restrict__ k,
                                  const int* __restrict__ pos_ids) {
    int idx = blockIdx.x * 256 + threadIdx.x;
    if (idx >= BHN * SS * 8) return;
    int c = idx & 7;
    int s = (idx >> 3) & 2047;
    int bh = idx >> 14;
    int b = bh >> 5;
    int pos = pos_ids[b * SS + s];
    int d0 = c * 8;
    size_t rb = ((size_t)bh * SS + s) * DD;

    float xq[8], yq[8], xk[8], yk[8], cs[8], sn[8];
    *(float4*)&xq[0] = *(const float4*)&q[rb + d0];
    *(float4*)&xq[4] = *(const float4*)&q[rb + d0 + 4];
    *(float4*)&yq[0] = *(const float4*)&q[rb + d0 + 64];
    *(float4*)&yq[4] = *(const float4*)&q[rb + d0 + 68];
    *(float4*)&xk[0] = *(const float4*)&k[rb + d0];
    *(float4*)&xk[4] = *(const float4*)&k[rb + d0 + 4];
    *(float4*)&yk[0] = *(const float4*)&k[rb + d0 + 64];
    *(float4*)&yk[4] = *(const float4*)&k[rb + d0 + 68];
    #pragma unroll
    for (int i = 0; i < 8; i++) {
        cs[i] = g_cos[pos * 64 + d0 + i];
        sn[i] = g_sin[pos * 64 + d0 + i];
    }

    float loq[8], upq[8], lok[8], upk[8];
    #pragma unroll
    for (int i = 0; i < 8; i++) {
        loq[i] = __fsub_rn(__fmul_rn(xq[i], cs[i]), __fmul_rn(yq[i], sn[i]));
        upq[i] = __fadd_rn(__fmul_rn(yq[i], cs[i]), __fmul_rn(xq[i], sn[i]));
        lok[i] = __fsub_rn(__fmul_rn(xk[i], cs[i]), __fmul_rn(yk[i], sn[i]));
        upk[i] = __fadd_rn(__fmul_rn(yk[i], cs[i]), __fmul_rn(xk[i], sn[i]));
    }

    *(float4*)&g_krot[rb + d0]      = *(float4*)&lok[0];
    *(float4*)&g_krot[rb + d0 + 4]  = *(float4*)&lok[4];
    *(float4*)&g_krot[rb + d0 + 64] = *(float4*)&upk[0];
    *(float4*)&g_krot[rb + d0 + 68] = *(float4*)&upk[4];

    size_t rowb = ((size_t)bh * SS + s) * 16;
    int pcl = c ^ (s & 7);
    int pcu = 8 + pcl;
    g_qb[rowb + pcl] = pack8h(loq);
    g_qb[rowb + pcu] = pack8h(upq);
    g_kb[rowb + pcl] = pack8h(lok);
    g_kb[rowb + pcu] = pack8h(upk);
}

// ---------------------------------------------------------------------------
// V fp16 plane.
// ---------------------------------------------------------------------------
__global__ void v_split_kernel(const float* __restrict__ v) {
    int idx = blockIdx.x * 256 + threadIdx.x;
    if (idx >= BHN * SS * 16) return;
    int c = idx & 15;
    int s = (idx >> 4) & 2047;
    int bh = idx >> 15;
    size_t rb = ((size_t)bh * SS + s) * DD;
    float x[8];
    *(float4*)&x[0] = *(const float4*)&v[rb + c * 8];
    *(float4*)&x[4] = *(const float4*)&v[rb + c * 8 + 4];
    size_t rowb = ((size_t)bh * SS + s) * 16;
    int pc = c ^ (s & 7);
    g_vb[rowb + pc] = pack8h(x);
}

// ---------------------------------------------------------------------------
// Mega kernel: role by blockIdx.x.
//  [0, NB_ATTN):          flash attention, BM=64, single-pass fp16 MMA
//  [NB_ATTN, +NB_KQP):    kq_partial (per-channel partial top-17)
//  [+NB_KQP, +NB_VQ):     vquant (4 warps x 64 tokens)
// ---------------------------------------------------------------------------
#define STG 32768
#define SM_TOT 65536

__global__ __launch_bounds__(128, 3)
void mega_kernel(const uint4* __restrict__ pqb, const uint4* __restrict__ pkb,
                 const uint4* __restrict__ pvb, const float* __restrict__ kr,
                 const float* __restrict__ vsrc, float* __restrict__ out) {
    const int bid = (int)blockIdx.x;
    const int tid = threadIdx.x;

    if (bid < NB_ATTN) {
        // ================= attention =================
        extern __shared__ char smc[];
        const int w = tid >> 5, l = tid & 31;
        const int qb = 31 - (bid >> 6);      // qb-major, heavy first
        const int bh = bid & 63;
        const uint32_t sb = smem_u32(smc);

        const int rowmin = qb * 64 + w * 16;
        const int row0 = rowmin + (l >> 2);
        const int aR = ((l >> 3) & 1) * 8 + (l & 7);
        const int aK = ((l >> 4) & 1) * 8;
        const int bR = ((l >> 4) & 1) * 8 + (l & 7);
        const int bK = ((l >> 3) & 1) * 8;
        const int vR = ((l >> 3) & 1) * 8 + (l & 7);
        const int vD = ((l >> 4) & 1) * 8;
        const float sc = 0.088388347648318447f * 1.4426950408889634f;
        const int nt = qb + 1;

        // Stage Q (16KB) via cp.async, hoist fragments
        {
            size_t qsrc = ((size_t)bh * SS + (size_t)qb * 64) * 16;
            #pragma unroll
            for (int j = 0; j < 8; j++) {
                int i = tid + j * 128;     // 0..1023
                CP_ASYNC16(sb + i * 16, pqb + qsrc + i);
            }
            CP_COMMIT();
            CP_WAIT0();
        }
        __syncthreads();

        uint32_t qh[8][4];
        #pragma unroll
        for (int ks = 0; ks < 8; ks++)
            LDSM4(qh[ks], sb + soff(w * 16 + aR, ks * 16 + aK));
        __syncthreads();

        // Prefetch tile 0
        {
            size_t src = (size_t)bh * SS * 16;
            #pragma unroll
            for (int j = 0; j < 8; j++) {
                int i = tid + j * 128;
                CP_ASYNC16(sb + i * 16,         pkb + src + i);
                CP_ASYNC16(sb + 16384 + i * 16, pvb + src + i);
            }
            CP_COMMIT();
        }

        float o_[16][4];
        #pragma unroll
        for (int i = 0; i < 16; i++)
            #pragma unroll
            for (int j = 0; j < 4; j++) o_[i][j] = 0.0f;
        float lsum0 = 0.0f, lsum1 = 0.0f;

        for (int t = 0; t < nt; t++) {
            if (t + 1 < nt) {
                uint32_t st = sb + ((t + 1) & 1) * STG;
                size_t src = ((size_t)bh * SS + (size_t)(t + 1) * 64) * 16;
                #pragma unroll
                for (int j = 0; j < 8; j++) {
                    int i = tid + j * 128;
                    CP_ASYNC16(st + i * 16,         pkb + src + i);
                    CP_ASYNC16(st + 16384 + i * 16, pvb + src + i);
                }
                CP_COMMIT();
                CP_WAIT1();
            } else {
                CP_WAIT0();
            }
            __syncthreads();

            const uint32_t st = sb + (t & 1) * STG;

            // S = Q K^T (single pass)
            float s_[8][4];
            #pragma unroll
            for (int i = 0; i < 8; i++)
                #pragma unroll
                for (int j = 0; j < 4; j++) s_[i][j] = 0.0f;

            #pragma unroll
            for (int ks = 0; ks < 8; ks++) {
                #pragma unroll
                for (int n0 = 0; n0 < 4; n0++) {
                    uint32_t kh_[4];
                    LDSM4(kh_, st + soff(n0 * 16 + bR, ks * 16 + bK));
                    MMAH16816(s_[2*n0],   qh[ks][0],qh[ks][1],qh[ks][2],qh[ks][3], kh_[0], kh_[1]);
                    MMAH16816(s_[2*n0+1], qh[ks][0],qh[ks][1],qh[ks][2],qh[ks][3], kh_[2], kh_[3]);
                }
            }

            // softmax (no rescale), P fragments (fp16, single)
            const bool needmask = (64 * t + 63 > rowmin);
            uint32_t phi[8][2];
            const int colb = 64 * t + 2 * (l & 3);
            #pragma unroll
            for (int n2 = 0; n2 < 8; n2++) {
                float p0 = ex2f(s_[n2][0] * sc);
                float p1 = ex2f(s_[n2][1] * sc);
                float p2 = ex2f(s_[n2][2] * sc);
                float p3 = ex2f(s_[n2][3] * sc);
                if (needmask) {
                    int c0 = colb + 8 * n2;
                    if (c0     > row0)     p0 = 0.0f;
                    if (c0 + 1 > row0)     p1 = 0.0f;
                    if (c0     > row0 + 8) p2 = 0.0f;
                    if (c0 + 1 > row0 + 8) p3 = 0.0f;
                }
                lsum0 += p0 + p1;
                lsum1 += p2 + p3;
                phi[n2][0] = pk2h(p0, p1);
                phi[n2][1] = pk2h(p2, p3);
            }

            // O += P V (single pass)
            #pragma unroll
            for (int ks = 0; ks < 4; ks++) {
                uint32_t A0 = phi[2*ks][0], A1 = phi[2*ks][1];
                uint32_t A2 = phi[2*ks+1][0], A3 = phi[2*ks+1][1];
                #pragma unroll
                for (int d0 = 0; d0 < 8; d0++) {
                    uint32_t vh_[4];
                    LDSM4T(vh_, st + 16384 + soff(ks * 16 + vR, d0 * 16 + vD));
                    MMAH16816(o_[2*d0],   A0,A1,A2,A3, vh_[0], vh_[1]);
                    MMAH16816(o_[2*d0+1], A0,A1,A2,A3, vh_[2], vh_[3]);
                }
            }
            __syncthreads();
        }

        // epilogue
        lsum0 += __shfl_xor_sync(0xffffffffu, lsum0, 1);
        lsum0 += __shfl_xor_sync(0xffffffffu, lsum0, 2);
        lsum1 += __shfl_xor_sync(0xffffffffu, lsum1, 1);
        lsum1 += __shfl_xor_sync(0xffffffffu, lsum1, 2);
        float inv0 = 1.0f / lsum0;
        float inv1 = 1.0f / lsum1;
        size_t rbase = OFF_ATTN + ((size_t)bh * SS + row0) * DD;
        #pragma unroll
        for (int n2 = 0; n2 < 16; n2++) {
            int d = n2 * 8 + 2 * (l & 3);
            float2 a = {o_[n2][0] * inv0, o_[n2][1] * inv0};
            float2 b = {o_[n2][2] * inv1, o_[n2][3] * inv1};
            *(float2*)&out[rbase + d] = a;
            *(float2*)&out[rbase + 8 * DD + d] = b;
        }
    } else if (bid < NB_ATTN + NB_KQP) {
        // ================= kq_partial =================
        int kb2 = bid - NB_ATTN;
        int bh = kb2 >> 4, ch = kb2 & 15, d = tid;
        unsigned long long a[17];
        #pragma unroll
        for (int i = 0; i < 17; i++) a[i] = 0ull;

        int s0 = ch * 128;
        const float* p = kr + ((size_t)bh * SS + s0) * DD + d;
        int ibeg = (ch == 0) ? 4 : 0;
        for (int i = ibeg; i < 128; i++) {
            float v = p[(size_t)i * DD];
            unsigned ab = __float_as_uint(fabsf(v));
            unsigned long long key = ((unsigned long long)ab << 32) | (unsigned)(4095 - (s0 + i));
            ins17(a, key);
        }
        unsigned long long* dst = g_pk + (((size_t)bh * DD + d) * 16 + ch) * 17;
        #pragma unroll
        for (int i = 0; i < 17; i++) dst[i] = a[i];
    } else {
        // ================= vquant =================
        int vb2 = bid - NB_ATTN - NB_KQP;
        int wi = tid >> 5, lane = tid & 31;
        for (int it = 0; it < 64; it++) {
            int gwarp = vb2 * 256 + wi * 64 + it;
            int s = gwarp & (SS - 1);

            const float* row = vsrc + (size_t)gwarp * DD;
            float4 x = *(const float4*)(row + lane * 4);
            float vals[4] = {x.x, x.y, x.z, x.w};

            int tidx[4] = {0, 1, 2, 3};
            float tval[4] = {0.0f, 0.0f, 0.0f, 0.0f};
            float absmax = 0.0f;
            bool sink = (s < 4);

            if (!sink) {
                unsigned used = 0u;
                unsigned long long keys[4];
                #pragma unroll
                for (int i = 0; i < 4; i++) {
                    unsigned ab = __float_as_uint(fabsf(vals[i]));
                    keys[i] = ((unsigned long long)ab << 32) | (unsigned)(127 - (lane * 4 + i));
                }
                for (int rnd = 0; rnd < 5; rnd++) {
                    unsigned long long best = 0ull;
                    #pragma unroll
                    for (int i = 0; i < 4; i++)
                        if (!((used >> i) & 1u) && keys[i] > best) best = keys[i];
                    #pragma unroll
                    for (int off = 16; off >= 1; off >>= 1) {
                        unsigned long long o2 = __shfl_xor_sync(0xffffffffu, best, off);
                        if (o2 > best) best = o2;
                    }
                    int gidx = 127 - (int)(unsigned)(best & 0xffffffffull);
                    float ab = __uint_as_float((unsigned)(best >> 32));
                    int owner = gidx >> 2, slot = gidx & 3;
                    if (lane == owner) used |= (1u << slot);
                    if (rnd < 4) {
                        float cand = (slot == 0) ? vals[0] : (slot == 1) ? vals[1]
                                   : (slot == 2) ? vals[2] : vals[3];
                        float sv = __shfl_sync(0xffffffffu, cand, owner);
                        tidx[rnd] = gidx;
                        tval[rnd] = sv;
                    } else {
                        absmax = ab;
                    }
                }
            }

            float scale = fmaxf(absmax, 1e-8f) / 127.0f;

            float q[4];
            #pragma unroll
            for (int i = 0; i < 4; i++) {
                int gi = lane * 4 + i;
                bool zero = sink | (gi == tidx[0]) | (gi == tidx[1]) | (gi == tidx[2]) | (gi == tidx[3]);
                if (zero) {
                    q[i] = 0.0f;
                } else {
                    float r = rintf(vals[i] / scale);
                    q[i] = fminf(fmaxf(r, -127.0f), 127.0f);
                }
            }
            float4 qo = {q[0], q[1], q[2], q[3]};
            *(float4*)&out[OFF_VQ + (size_t)gwarp * DD + lane * 4] = qo;

            if (lane == 0) {
                out[OFF_VSCALE + gwarp] = scale;
                #pragma unroll
                for (int t = 0; t < 4; t++) {
                    out[OFF_VSPV + (size_t)gwarp * 4 + t] = tval[t];
                    out[OFF_VSPI + (size_t)gwarp * 4 + t] = (float)tidx[t];
                }
            }
        }
    }
}

// ---------------------------------------------------------------------------
// kq_merge: fold 16 partials -> exact top-17; scale, sp outputs, bitmap.
// ---------------------------------------------------------------------------
__global__ void kq_merge(const float* __restrict__ kr, float* __restrict__ out) {
    int bh = blockIdx.x, d = threadIdx.x;
    unsigned long long a[17];
    #pragma unroll
    for (int i = 0; i < 17; i++) a[i] = 0ull;

    const unsigned long long* pk = g_pk + ((size_t)bh * DD + d) * 16 * 17;
    for (int t = 0; t < 16 * 17; t++) ins17(a, pk[t]);

    float absmax = __uint_as_float((unsigned)(a[16] >> 32));
    float scale = fmaxf(absmax, 1e-8f) / 127.0f;
    out[OFF_KSCALE + (size_t)bh * DD + d] = scale;

    size_t sp = ((size_t)bh * DD + d) * 16;
    int idxs[16];
    #pragma unroll
    for (int i = 0; i < 16; i++) {
        int s = 4095 - (int)(unsigned)(a[i] & 0xFFFFFFFFull);
        idxs[i] = s;
        out[OFF_KSPI + sp + i] = (float)s;
        out[OFF_KSPV + sp + i] = kr[((size_t)bh * SS + s) * DD + d];
    }

    unsigned m[64];
    for (int w = 0; w < 64; w++) m[w] = 0u;
    #pragma unroll
    for (int i = 0; i < 16; i++) m[idxs[i] >> 5] |= (1u << (idxs[i] & 31));
    for (int w = 0; w < 64; w++)
        g_mask[((size_t)bh * 64 + w) * DD + d] = m[w];
}

__global__ __launch_bounds__(256)
void kq_write(const float* __restrict__ kr, float* __restrict__ out) {
    __shared__ unsigned smask[512];
    __shared__ float sscale[128];
    int bh = blockIdx.x, scn = blockIdx.y;
    int tid = threadIdx.x;

    for (int i = tid; i < 512; i += 256) {
        int w4 = i >> 7, d = i & 127;
        smask[i] = g_mask[((size_t)bh * 64 + scn * 4 + w4) * DD + d];
    }
    if (tid < 128) sscale[tid] = out[OFF_KSCALE + (size_t)bh * DD + tid];
    __syncthreads();

    for (int u = tid; u < 4096; u += 256) {
        int r = u >> 5, d4 = u & 31;
        int s = scn * 128 + r;
        size_t off = ((size_t)bh * SS + s) * DD + d4 * 4;
        float4 v = *(const float4*)(kr + off);
        int w4 = r >> 5;
        int bit = s & 31;
        float vv[4] = {v.x, v.y, v.z, v.w};
        float q[4];
        #pragma unroll
        for (int j = 0; j < 4; j++) {
            int dd = d4 * 4 + j;
            bool z = (s < 4) || ((smask[w4 * 128 + dd] >> bit) & 1u);
            if (z) {
                q[j] = 0.0f;
            } else {
                float r2 = rintf(vv[j] / sscale[dd]);
                q[j] = fminf(fmaxf(r2, -127.0f), 127.0f);
            }
        }
        float4 qo = {q[0], q[1], q[2], q[3]};
        *(float4*)&out[OFF_KQ + off] = qo;
    }
}

// ---------------------------------------------------------------------------
extern "C" void kernel_launch(void* const* d_in, const int* in_sizes, int n_in,
                              void* d_out, int out_size) {
    const float* q = (const float*)d_in[0];
    const float* k = (const float*)d_in[1];
    const float* v = (const float*)d_in[2];
    const int* pos = (const int*)d_in[3];
    float* out = (float*)d_out;

    float* krot; cudaGetSymbolAddress((void**)&krot, g_krot);
    uint4 *pqb, *pkb, *pvb;
    cudaGetSymbolAddress((void**)&pqb, g_qb);
    cudaGetSymbolAddress((void**)&pkb, g_kb);
    cudaGetSymbolAddress((void**)&pvb, g_vb);

    // 1. inv_freq + cos/sin table
    invf_kernel<<<1, 64>>>();
    table_kernel<<<SS, 64>>>();

    // 2. Fused RoPE + fp16 planes (Q, K) + krot f32
    rope_split_kernel<<<(BHN * SS * 8 + 255) / 256, 256>>>(q, k, pos);

    // 3. V fp16 plane
    v_split_kernel<<<(BHN * SS * 16 + 255) / 256, 256>>>(v);

    // 4. Mega: attention + kq_partial + vquant (independent, overlapped)
    {
        cudaFuncSetAttribute(mega_kernel, cudaFuncAttributeMaxDynamicSharedMemorySize, SM_TOT);
        mega_kernel<<<NB_TOT, 128, SM_TOT>>>(pqb, pkb, pvb, krot, v, out);
    }

    // 5. K quant: merge + quantize
    kq_merge<<<BHN, 128>>>(krot, out);
    {
        dim3 gw(BHN, 16);
        kq_write<<<gw, 256>>>(krot, out);
    }
}